// round 1
// baseline (speedup 1.0000x reference)
#include <cuda_runtime.h>
#include <math.h>

// ---------------------------------------------------------------------------
// Problem constants (fixed shapes)
// ---------------------------------------------------------------------------
constexpr int Bc   = 2;
constexpr int Sc   = 2048;
constexpr int Hc   = 2048;
constexpr int KVHc = 8;
constexpr int QPKc = 4;
constexpr int Dc   = 64;
constexpr int KVc  = 512;    // KVH * D
constexpr int FFc  = 8192;
constexpr int MR   = Bc * Sc;          // 4096 rows
constexpr int NHEADZ = Bc * KVHc * QPKc; // 64 head instances

// ---------------------------------------------------------------------------
// Scratch (device globals; no runtime allocation allowed)
// ---------------------------------------------------------------------------
__device__ float g_h  [(size_t)MR * Hc];        //  33.5 MB  LN1 out
__device__ float g_q  [(size_t)MR * Hc];        //  33.5 MB
__device__ float g_k  [(size_t)MR * KVc];       //   8.4 MB
__device__ float g_v  [(size_t)MR * KVc];       //   8.4 MB
__device__ float g_sc [(size_t)NHEADZ * Sc * Sc]; // 1 GiB scores
__device__ float g_o  [(size_t)MR * Hc];        //  33.5 MB
__device__ float g_x1 [(size_t)MR * Hc];        //  33.5 MB
__device__ float g_h2 [(size_t)MR * Hc];        //  33.5 MB
__device__ float g_m1 [(size_t)MR * FFc];       // 134 MB

// ---------------------------------------------------------------------------
// LayerNorm: one block per row of 2048, 256 threads, 8 elems/thread
// ---------------------------------------------------------------------------
__global__ void ln_kernel(const float* __restrict__ x,
                          const float* __restrict__ g,
                          const float* __restrict__ b,
                          float* __restrict__ out)
{
    const int HD = Hc;
    const long long row = blockIdx.x;
    const float* xr = x + row * HD;
    float* outr = out + row * HD;
    const int tid = threadIdx.x; // 256

    float4 v0 = *(const float4*)(xr + tid * 8);
    float4 v1 = *(const float4*)(xr + tid * 8 + 4);
    float s  = v0.x + v0.y + v0.z + v0.w + v1.x + v1.y + v1.z + v1.w;
    float sq = v0.x*v0.x + v0.y*v0.y + v0.z*v0.z + v0.w*v0.w
             + v1.x*v1.x + v1.y*v1.y + v1.z*v1.z + v1.w*v1.w;

    #pragma unroll
    for (int o = 16; o; o >>= 1) {
        s  += __shfl_xor_sync(0xffffffffu, s,  o);
        sq += __shfl_xor_sync(0xffffffffu, sq, o);
    }
    __shared__ float ss[8], ssq[8];
    if ((tid & 31) == 0) { ss[tid >> 5] = s; ssq[tid >> 5] = sq; }
    __syncthreads();
    float ts = 0.f, tsq = 0.f;
    #pragma unroll
    for (int i = 0; i < 8; i++) { ts += ss[i]; tsq += ssq[i]; }

    const float mu  = ts * (1.0f / HD);
    const float var = tsq * (1.0f / HD) - mu * mu;
    const float inv = rsqrtf(var + 1e-5f);

    float4 gg0 = *(const float4*)(g + tid * 8);
    float4 gg1 = *(const float4*)(g + tid * 8 + 4);
    float4 bb0 = *(const float4*)(b + tid * 8);
    float4 bb1 = *(const float4*)(b + tid * 8 + 4);

    float4 o0, o1;
    o0.x = (v0.x - mu) * inv * gg0.x + bb0.x;
    o0.y = (v0.y - mu) * inv * gg0.y + bb0.y;
    o0.z = (v0.z - mu) * inv * gg0.z + bb0.z;
    o0.w = (v0.w - mu) * inv * gg0.w + bb0.w;
    o1.x = (v1.x - mu) * inv * gg1.x + bb1.x;
    o1.y = (v1.y - mu) * inv * gg1.y + bb1.y;
    o1.z = (v1.z - mu) * inv * gg1.z + bb1.z;
    o1.w = (v1.w - mu) * inv * gg1.w + bb1.w;
    *(float4*)(outr + tid * 8)     = o0;
    *(float4*)(outr + tid * 8 + 4) = o1;
}

// ---------------------------------------------------------------------------
// Softmax over last dim (2048), one block per row, row kept in registers
// ---------------------------------------------------------------------------
__global__ void softmax_kernel(float* __restrict__ scores)
{
    const long long row = blockIdx.x;
    float* p = scores + row * (long long)Sc;
    const int tid = threadIdx.x; // 256

    float4 v0 = *(const float4*)(p + tid * 8);
    float4 v1 = *(const float4*)(p + tid * 8 + 4);

    float mx = fmaxf(fmaxf(fmaxf(v0.x, v0.y), fmaxf(v0.z, v0.w)),
                     fmaxf(fmaxf(v1.x, v1.y), fmaxf(v1.z, v1.w)));
    #pragma unroll
    for (int o = 16; o; o >>= 1) mx = fmaxf(mx, __shfl_xor_sync(0xffffffffu, mx, o));
    __shared__ float sm[8];
    if ((tid & 31) == 0) sm[tid >> 5] = mx;
    __syncthreads();
    float tmx = sm[0];
    #pragma unroll
    for (int i = 1; i < 8; i++) tmx = fmaxf(tmx, sm[i]);
    __syncthreads();

    v0.x = expf(v0.x - tmx); v0.y = expf(v0.y - tmx);
    v0.z = expf(v0.z - tmx); v0.w = expf(v0.w - tmx);
    v1.x = expf(v1.x - tmx); v1.y = expf(v1.y - tmx);
    v1.z = expf(v1.z - tmx); v1.w = expf(v1.w - tmx);
    float s = v0.x + v0.y + v0.z + v0.w + v1.x + v1.y + v1.z + v1.w;
    #pragma unroll
    for (int o = 16; o; o >>= 1) s += __shfl_xor_sync(0xffffffffu, s, o);
    __shared__ float sp[8];
    if ((tid & 31) == 0) sp[tid >> 5] = s;
    __syncthreads();
    float ts = 0.f;
    #pragma unroll
    for (int i = 0; i < 8; i++) ts += sp[i];
    const float inv = 1.0f / ts;

    v0.x *= inv; v0.y *= inv; v0.z *= inv; v0.w *= inv;
    v1.x *= inv; v1.y *= inv; v1.z *= inv; v1.w *= inv;
    *(float4*)(p + tid * 8)     = v0;
    *(float4*)(p + tid * 8 + 4) = v1;
}

// ---------------------------------------------------------------------------
// Register-blocked SGEMM template.
//   BM=128 fixed, BN in {64,128}, BK=8, 256 threads, thread tile TM=8 x TN=BN/16
//   TRANSB: 0 -> B is [K,N] row-major;  1 -> B is [N,K] row-major (only BN=128)
//   EPI: 0 plain, 1 +bias, 2 res+acc+bias, 3 gelu(acc+bias), 4 acc*scale+mask
//   MODE: 0 plain (no batch), 1 scores batching, 2 PV batching (blockIdx.z)
// ---------------------------------------------------------------------------
template<int BN, int TRANSB, int EPI, int MODE>
__global__ void gemm_kernel(const float* __restrict__ A, int lda,
                            const float* __restrict__ Bm, int ldb,
                            float* __restrict__ C, int ldc,
                            int M, int N, int K,
                            const float* __restrict__ bias,
                            const float* __restrict__ res,
                            const float* __restrict__ mask,
                            float scale)
{
    constexpr int BM = 128, BK = 8, TM = 8;
    constexpr int TN = BN / 16;

    __shared__ float As[BK][BM];
    __shared__ float Bs[BK][BN];

    const int tid = threadIdx.x;
    const int z = blockIdx.z;

    const float* maskp = mask;
    if (MODE == 1) {
        const int bi = z >> 5, kvh = (z >> 2) & 7, qpk = z & 3;
        A  += (long long)bi * Sc * Hc + kvh * (QPKc * Dc) + qpk * Dc;
        Bm += (long long)bi * Sc * KVc + kvh * Dc;
        C  += (long long)z * Sc * Sc;
        maskp = mask + (long long)bi * Sc;
    } else if (MODE == 2) {
        const int bi = z >> 5, kvh = (z >> 2) & 7, qpk = z & 3;
        A  += (long long)z * Sc * Sc;
        Bm += (long long)bi * Sc * KVc + kvh * Dc;
        C  += (long long)bi * Sc * Hc + (kvh * QPKc + qpk) * Dc;
    }

    const int cRow = blockIdx.y;
    const int cCol = blockIdx.x;
    const int threadRow = tid >> 4;   // 0..15
    const int threadCol = tid & 15;   // 0..15

    float acc[TM][TN];
    #pragma unroll
    for (int i = 0; i < TM; i++)
        #pragma unroll
        for (int j = 0; j < TN; j++) acc[i][j] = 0.f;

    const int innerRowA = tid >> 1;         // 0..127
    const int innerColA = (tid & 1) * 4;    // 0 or 4
    const int innerRowB = tid / (BN / 4);
    const int innerColB = (tid % (BN / 4)) * 4;

    const float* Ab = A + (long long)(cRow * BM + innerRowA) * lda + innerColA;

    for (int kt = 0; kt < K; kt += BK) {
        // ---- load A tile 128x8 (transpose into As[k][m]) ----
        {
            float4 a4 = *(const float4*)(Ab + kt);
            As[innerColA + 0][innerRowA] = a4.x;
            As[innerColA + 1][innerRowA] = a4.y;
            As[innerColA + 2][innerRowA] = a4.z;
            As[innerColA + 3][innerRowA] = a4.w;
        }
        // ---- load B tile 8xBN ----
        if (TRANSB == 0) {
            if (BN == 128 || tid < 2 * BN) {
                float4 b4 = *(const float4*)(Bm + (long long)(kt + innerRowB) * ldb
                                             + cCol * BN + innerColB);
                *(float4*)&Bs[innerRowB][innerColB] = b4;
            }
        } else {
            // B is [N,K] row-major; Bs[k][n] = B[(cCol*BN+n)*ldb + kt + k]
            const int n  = tid >> 1;          // 0..127 (BN==128)
            const int kb = (tid & 1) * 4;
            float4 b4 = *(const float4*)(Bm + (long long)(cCol * BN + n) * ldb + kt + kb);
            Bs[kb + 0][n] = b4.x;
            Bs[kb + 1][n] = b4.y;
            Bs[kb + 2][n] = b4.z;
            Bs[kb + 3][n] = b4.w;
        }
        __syncthreads();

        #pragma unroll
        for (int k = 0; k < BK; k++) {
            float ra[TM], rb[TN];
            #pragma unroll
            for (int i = 0; i < TM; i += 4)
                *(float4*)&ra[i] = *(const float4*)&As[k][threadRow * TM + i];
            #pragma unroll
            for (int j = 0; j < TN; j += 4)
                *(float4*)&rb[j] = *(const float4*)&Bs[k][threadCol * TN + j];
            #pragma unroll
            for (int i = 0; i < TM; i++)
                #pragma unroll
                for (int j = 0; j < TN; j++)
                    acc[i][j] = fmaf(ra[i], rb[j], acc[i][j]);
        }
        __syncthreads();
    }

    // ---- epilogue ----
    #pragma unroll
    for (int i = 0; i < TM; i++) {
        const int row = cRow * BM + threadRow * TM + i;
        #pragma unroll
        for (int j = 0; j < TN; j++) {
            const int col = cCol * BN + threadCol * TN + j;
            float v = acc[i][j];
            if (EPI == 1) {
                v += bias[col];
            } else if (EPI == 2) {
                v += bias[col] + res[(long long)row * ldc + col];
            } else if (EPI == 3) {
                v += bias[col];
                v = 0.5f * v * (1.0f + erff(v * 0.70710678118654752f));
            } else if (EPI == 4) {
                v = v * scale + maskp[col];
            }
            C[(long long)row * ldc + col] = v;
        }
    }
}

// ---------------------------------------------------------------------------
// Launch sequence
// ---------------------------------------------------------------------------
extern "C" void kernel_launch(void* const* d_in, const int* in_sizes, int n_in,
                              void* d_out, int out_size)
{
    const float* x    = (const float*)d_in[0];
    const float* mask = (const float*)d_in[1];
    const float* Wq   = (const float*)d_in[2];
    const float* bq   = (const float*)d_in[3];
    const float* Wk   = (const float*)d_in[4];
    const float* bk   = (const float*)d_in[5];
    const float* Wv   = (const float*)d_in[6];
    const float* bv   = (const float*)d_in[7];
    const float* Wo   = (const float*)d_in[8];
    const float* bo   = (const float*)d_in[9];
    const float* W1   = (const float*)d_in[10];
    const float* b1   = (const float*)d_in[11];
    const float* W2   = (const float*)d_in[12];
    const float* b2   = (const float*)d_in[13];
    const float* g1   = (const float*)d_in[14];
    const float* be1  = (const float*)d_in[15];
    const float* g2   = (const float*)d_in[16];
    const float* be2  = (const float*)d_in[17];
    float* out = (float*)d_out;

    float *h, *q, *kq, *vq, *sc, *o, *x1, *h2, *m1;
    cudaGetSymbolAddress((void**)&h,  g_h);
    cudaGetSymbolAddress((void**)&q,  g_q);
    cudaGetSymbolAddress((void**)&kq, g_k);
    cudaGetSymbolAddress((void**)&vq, g_v);
    cudaGetSymbolAddress((void**)&sc, g_sc);
    cudaGetSymbolAddress((void**)&o,  g_o);
    cudaGetSymbolAddress((void**)&x1, g_x1);
    cudaGetSymbolAddress((void**)&h2, g_h2);
    cudaGetSymbolAddress((void**)&m1, g_m1);

    // 1) h = LN(x; g1, be1)
    ln_kernel<<<MR, 256>>>(x, g1, be1, h);

    // 2) q = h @ Wq + bq          [4096 x 2048 x 2048]
    gemm_kernel<128, 0, 1, 0><<<dim3(Hc / 128, MR / 128, 1), 256>>>(
        h, Hc, Wq, Hc, q, Hc, MR, Hc, Hc, bq, nullptr, nullptr, 0.f);

    // 3) k = h @ Wk + bk          [4096 x 512 x 2048]
    gemm_kernel<128, 0, 1, 0><<<dim3(KVc / 128, MR / 128, 1), 256>>>(
        h, Hc, Wk, KVc, kq, KVc, MR, KVc, Hc, bk, nullptr, nullptr, 0.f);

    // 4) v = h @ Wv + bv
    gemm_kernel<128, 0, 1, 0><<<dim3(KVc / 128, MR / 128, 1), 256>>>(
        h, Hc, Wv, KVc, vq, KVc, MR, KVc, Hc, bv, nullptr, nullptr, 0.f);

    // 5) scores[z] = (Q_z @ K_z^T) * 1/8 + mask     [64 x (2048 x 2048 x 64)]
    gemm_kernel<128, 1, 4, 1><<<dim3(Sc / 128, Sc / 128, NHEADZ), 256>>>(
        q, Hc, kq, KVc, sc, Sc, Sc, Sc, Dc, nullptr, nullptr, mask, 0.125f);

    // 6) softmax rows
    softmax_kernel<<<(unsigned)((long long)NHEADZ * Sc), 256>>>(sc);

    // 7) o[z] = scores[z] @ V_z                      [64 x (2048 x 64 x 2048)]
    gemm_kernel<64, 0, 0, 2><<<dim3(1, Sc / 128, NHEADZ), 256>>>(
        sc, Sc, vq, KVc, o, Hc, Sc, Dc, Sc, nullptr, nullptr, nullptr, 0.f);

    // 8) x1 = x + o @ Wo + bo
    gemm_kernel<128, 0, 2, 0><<<dim3(Hc / 128, MR / 128, 1), 256>>>(
        o, Hc, Wo, Hc, x1, Hc, MR, Hc, Hc, bo, x, nullptr, 0.f);

    // 9) h2 = LN(x1; g2, be2)
    ln_kernel<<<MR, 256>>>(x1, g2, be2, h2);

    // 10) m1 = gelu(h2 @ W1 + b1)   [4096 x 8192 x 2048]
    gemm_kernel<128, 0, 3, 0><<<dim3(FFc / 128, MR / 128, 1), 256>>>(
        h2, Hc, W1, FFc, m1, FFc, MR, FFc, Hc, b1, nullptr, nullptr, 0.f);

    // 11) out = x1 + m1 @ W2 + b2   [4096 x 2048 x 8192]
    gemm_kernel<128, 0, 2, 0><<<dim3(Hc / 128, MR / 128, 1), 256>>>(
        m1, FFc, W2, Hc, out, Hc, MR, Hc, FFc, b2, x1, nullptr, 0.f);
}

// round 2
// speedup vs baseline: 2.6111x; 2.6111x over previous
#include <cuda_runtime.h>
#include <math.h>
#include <stdint.h>

// ---------------------------------------------------------------------------
// Problem constants (fixed shapes)
// ---------------------------------------------------------------------------
constexpr int Bc   = 2;
constexpr int Sc   = 2048;
constexpr int Hc   = 2048;
constexpr int KVHc = 8;
constexpr int QPKc = 4;
constexpr int Dc   = 64;
constexpr int KVc  = 512;    // KVH * D
constexpr int FFc  = 8192;
constexpr int MR   = Bc * Sc;            // 4096 rows
constexpr int NHEADZ = Bc * KVHc * QPKc; // 64 head instances

// ---------------------------------------------------------------------------
// Scratch (device globals; no runtime allocation allowed)
// ---------------------------------------------------------------------------
__device__ float g_h  [(size_t)MR * Hc];
__device__ float g_q  [(size_t)MR * Hc];
__device__ float g_k  [(size_t)MR * KVc];
__device__ float g_v  [(size_t)MR * KVc];
__device__ float g_sc [(size_t)NHEADZ * Sc * Sc]; // 1 GiB scores
__device__ float g_o  [(size_t)MR * Hc];
__device__ float g_x1 [(size_t)MR * Hc];
__device__ float g_h2 [(size_t)MR * Hc];
__device__ float g_m1 [(size_t)MR * FFc];

// ---------------------------------------------------------------------------
// Helpers
// ---------------------------------------------------------------------------
__device__ __forceinline__ uint32_t f2tf32(float f) {
    uint32_t u;
    asm("cvt.rna.tf32.f32 %0, %1;" : "=r"(u) : "f"(f));
    return u;
}

__device__ __forceinline__ void mma_tf32(float* c, const uint32_t* a, const uint32_t* b) {
    asm volatile(
        "mma.sync.aligned.m16n8k8.row.col.f32.tf32.tf32.f32 "
        "{%0,%1,%2,%3}, {%4,%5,%6,%7}, {%8,%9}, {%0,%1,%2,%3};\n"
        : "+f"(c[0]), "+f"(c[1]), "+f"(c[2]), "+f"(c[3])
        : "r"(a[0]), "r"(a[1]), "r"(a[2]), "r"(a[3]),
          "r"(b[0]), "r"(b[1]));
}

// ---------------------------------------------------------------------------
// LayerNorm: one block per row of 2048, 256 threads, 8 elems/thread
// ---------------------------------------------------------------------------
__global__ void ln_kernel(const float* __restrict__ x,
                          const float* __restrict__ g,
                          const float* __restrict__ b,
                          float* __restrict__ out)
{
    const int HD = Hc;
    const long long row = blockIdx.x;
    const float* xr = x + row * HD;
    float* outr = out + row * HD;
    const int tid = threadIdx.x;

    float4 v0 = *(const float4*)(xr + tid * 8);
    float4 v1 = *(const float4*)(xr + tid * 8 + 4);
    float s  = v0.x + v0.y + v0.z + v0.w + v1.x + v1.y + v1.z + v1.w;
    float sq = v0.x*v0.x + v0.y*v0.y + v0.z*v0.z + v0.w*v0.w
             + v1.x*v1.x + v1.y*v1.y + v1.z*v1.z + v1.w*v1.w;

    #pragma unroll
    for (int o = 16; o; o >>= 1) {
        s  += __shfl_xor_sync(0xffffffffu, s,  o);
        sq += __shfl_xor_sync(0xffffffffu, sq, o);
    }
    __shared__ float ss[8], ssq[8];
    if ((tid & 31) == 0) { ss[tid >> 5] = s; ssq[tid >> 5] = sq; }
    __syncthreads();
    float ts = 0.f, tsq = 0.f;
    #pragma unroll
    for (int i = 0; i < 8; i++) { ts += ss[i]; tsq += ssq[i]; }

    const float mu  = ts * (1.0f / HD);
    const float var = tsq * (1.0f / HD) - mu * mu;
    const float inv = rsqrtf(var + 1e-5f);

    float4 gg0 = *(const float4*)(g + tid * 8);
    float4 gg1 = *(const float4*)(g + tid * 8 + 4);
    float4 bb0 = *(const float4*)(b + tid * 8);
    float4 bb1 = *(const float4*)(b + tid * 8 + 4);

    float4 o0, o1;
    o0.x = (v0.x - mu) * inv * gg0.x + bb0.x;
    o0.y = (v0.y - mu) * inv * gg0.y + bb0.y;
    o0.z = (v0.z - mu) * inv * gg0.z + bb0.z;
    o0.w = (v0.w - mu) * inv * gg0.w + bb0.w;
    o1.x = (v1.x - mu) * inv * gg1.x + bb1.x;
    o1.y = (v1.y - mu) * inv * gg1.y + bb1.y;
    o1.z = (v1.z - mu) * inv * gg1.z + bb1.z;
    o1.w = (v1.w - mu) * inv * gg1.w + bb1.w;
    *(float4*)(outr + tid * 8)     = o0;
    *(float4*)(outr + tid * 8 + 4) = o1;
}

// ---------------------------------------------------------------------------
// Softmax over last dim (2048), one block per row
// ---------------------------------------------------------------------------
__global__ void softmax_kernel(float* __restrict__ scores)
{
    const long long row = blockIdx.x;
    float* p = scores + row * (long long)Sc;
    const int tid = threadIdx.x;

    float4 v0 = *(const float4*)(p + tid * 8);
    float4 v1 = *(const float4*)(p + tid * 8 + 4);

    float mx = fmaxf(fmaxf(fmaxf(v0.x, v0.y), fmaxf(v0.z, v0.w)),
                     fmaxf(fmaxf(v1.x, v1.y), fmaxf(v1.z, v1.w)));
    #pragma unroll
    for (int o = 16; o; o >>= 1) mx = fmaxf(mx, __shfl_xor_sync(0xffffffffu, mx, o));
    __shared__ float sm[8];
    if ((tid & 31) == 0) sm[tid >> 5] = mx;
    __syncthreads();
    float tmx = sm[0];
    #pragma unroll
    for (int i = 1; i < 8; i++) tmx = fmaxf(tmx, sm[i]);
    __syncthreads();

    v0.x = expf(v0.x - tmx); v0.y = expf(v0.y - tmx);
    v0.z = expf(v0.z - tmx); v0.w = expf(v0.w - tmx);
    v1.x = expf(v1.x - tmx); v1.y = expf(v1.y - tmx);
    v1.z = expf(v1.z - tmx); v1.w = expf(v1.w - tmx);
    float s = v0.x + v0.y + v0.z + v0.w + v1.x + v1.y + v1.z + v1.w;
    #pragma unroll
    for (int o = 16; o; o >>= 1) s += __shfl_xor_sync(0xffffffffu, s, o);
    __shared__ float sp[8];
    if ((tid & 31) == 0) sp[tid >> 5] = s;
    __syncthreads();
    float ts = 0.f;
    #pragma unroll
    for (int i = 0; i < 8; i++) ts += sp[i];
    const float inv = 1.0f / ts;

    v0.x *= inv; v0.y *= inv; v0.z *= inv; v0.w *= inv;
    v1.x *= inv; v1.y *= inv; v1.z *= inv; v1.w *= inv;
    *(float4*)(p + tid * 8)     = v0;
    *(float4*)(p + tid * 8 + 4) = v1;
}

// ---------------------------------------------------------------------------
// tf32 tensor-core GEMM.
//   BM=128, BN in {128,64}, BK=16, 256 threads (8 warps).
//   BN=128: warp grid 2x4, warp tile 64x32 (MT=4,NT=4)
//   BN=64 : warp grid 4x2, warp tile 32x32 (MT=2,NT=4)
//   TRANSB: 0 -> B is [K,N] row-major;  1 -> B is [N,K] row-major
//   EPI: 0 plain, 1 +bias, 2 res+acc+bias, 3 gelu(acc+bias), 4 acc*scale+mask
//   MODE: 0 plain, 1 scores batching (z), 2 PV batching (z)
// ---------------------------------------------------------------------------
template<int BN, int TRANSB, int EPI, int MODE>
__global__ __launch_bounds__(256)
void gemm_tc(const float* __restrict__ A, int lda,
             const float* __restrict__ Bm, int ldb,
             float* __restrict__ C, int ldc,
             int M, int N, int K,
             const float* __restrict__ bias,
             const float* __restrict__ res,
             const float* __restrict__ mask,
             float scale)
{
    constexpr int BM = 128, BK = 16;
    constexpr int WM = (BN == 128) ? 64 : 32;
    constexpr int WN = 32;
    constexpr int MT = WM / 16;     // 4 or 2
    constexpr int NT = WN / 8;      // 4

    __shared__ float As[BK][BM + 8];
    __shared__ float Bs[BK][BN + 8];

    const int tid  = threadIdx.x;
    const int warp = tid >> 5;
    const int lane = tid & 31;
    const int g    = lane >> 2;  // 0..7
    const int tg   = lane & 3;   // 0..3
    const int wrow = (BN == 128) ? (warp >> 2) : (warp >> 1);
    const int wcol = (BN == 128) ? (warp & 3)  : (warp & 1);

    const int z = blockIdx.z;
    const float* maskp = mask;
    if (MODE == 1) {
        const int bi = z >> 5, kvh = (z >> 2) & 7, qpk = z & 3;
        A  += (long long)bi * Sc * Hc + kvh * (QPKc * Dc) + qpk * Dc;
        Bm += (long long)bi * Sc * KVc + kvh * Dc;
        C  += (long long)z * Sc * Sc;
        maskp = mask + (long long)bi * Sc;
    } else if (MODE == 2) {
        const int bi = z >> 5, kvh = (z >> 2) & 7, qpk = z & 3;
        A  += (long long)z * Sc * Sc;
        Bm += (long long)bi * Sc * KVc + kvh * Dc;
        C  += (long long)bi * Sc * Hc + (kvh * QPKc + qpk) * Dc;
    }

    const int cRow = blockIdx.y;
    const int cCol = blockIdx.x;

    float acc[MT][NT][4];
    #pragma unroll
    for (int mi = 0; mi < MT; mi++)
        #pragma unroll
        for (int ni = 0; ni < NT; ni++)
            #pragma unroll
            for (int r = 0; r < 4; r++) acc[mi][ni][r] = 0.f;

    constexpr int ACH = 2;                                   // 128*16/4/256
    constexpr int BCH = (TRANSB == 1) ? 2 : (BN == 128 ? 2 : 1);
    float4 pa[ACH], pb[BCH];

    const int ntiles = K / BK;

    // ---- prefetch tile 0 ----
    #pragma unroll
    for (int c = 0; c < ACH; c++) {
        int flat = c * 256 + tid;
        int r = flat >> 2, qq = flat & 3;
        pa[c] = *(const float4*)(A + (long long)(cRow * BM + r) * lda + qq * 4);
    }
    #pragma unroll
    for (int c = 0; c < BCH; c++) {
        int flat = c * 256 + tid;
        if (TRANSB == 1) {
            int n = flat >> 2, qq = flat & 3;
            pb[c] = *(const float4*)(Bm + (long long)(cCol * BN + n) * ldb + qq * 4);
        } else if (BN == 128) {
            int k = flat >> 5, qq = flat & 31;
            pb[c] = *(const float4*)(Bm + (long long)k * ldb + cCol * BN + qq * 4);
        } else {
            int k = flat >> 4, qq = flat & 15;
            pb[c] = *(const float4*)(Bm + (long long)k * ldb + cCol * BN + qq * 4);
        }
    }

    for (int kt = 0; kt < ntiles; ++kt) {
        // ---- store prefetched tile to smem ----
        #pragma unroll
        for (int c = 0; c < ACH; c++) {
            int flat = c * 256 + tid;
            int r = flat >> 2, qq = flat & 3;
            As[qq * 4 + 0][r] = pa[c].x;
            As[qq * 4 + 1][r] = pa[c].y;
            As[qq * 4 + 2][r] = pa[c].z;
            As[qq * 4 + 3][r] = pa[c].w;
        }
        #pragma unroll
        for (int c = 0; c < BCH; c++) {
            int flat = c * 256 + tid;
            if (TRANSB == 1) {
                int n = flat >> 2, qq = flat & 3;
                Bs[qq * 4 + 0][n] = pb[c].x;
                Bs[qq * 4 + 1][n] = pb[c].y;
                Bs[qq * 4 + 2][n] = pb[c].z;
                Bs[qq * 4 + 3][n] = pb[c].w;
            } else if (BN == 128) {
                int k = flat >> 5, qq = flat & 31;
                *(float4*)&Bs[k][qq * 4] = pb[c];
            } else {
                int k = flat >> 4, qq = flat & 15;
                *(float4*)&Bs[k][qq * 4] = pb[c];
            }
        }
        __syncthreads();

        // ---- prefetch next tile (overlaps compute) ----
        if (kt + 1 < ntiles) {
            const int k0 = (kt + 1) * BK;
            #pragma unroll
            for (int c = 0; c < ACH; c++) {
                int flat = c * 256 + tid;
                int r = flat >> 2, qq = flat & 3;
                pa[c] = *(const float4*)(A + (long long)(cRow * BM + r) * lda + k0 + qq * 4);
            }
            #pragma unroll
            for (int c = 0; c < BCH; c++) {
                int flat = c * 256 + tid;
                if (TRANSB == 1) {
                    int n = flat >> 2, qq = flat & 3;
                    pb[c] = *(const float4*)(Bm + (long long)(cCol * BN + n) * ldb + k0 + qq * 4);
                } else if (BN == 128) {
                    int k = flat >> 5, qq = flat & 31;
                    pb[c] = *(const float4*)(Bm + (long long)(k0 + k) * ldb + cCol * BN + qq * 4);
                } else {
                    int k = flat >> 4, qq = flat & 15;
                    pb[c] = *(const float4*)(Bm + (long long)(k0 + k) * ldb + cCol * BN + qq * 4);
                }
            }
        }

        // ---- compute: 2 k-steps of 8 ----
        #pragma unroll
        for (int kk = 0; kk < BK; kk += 8) {
            uint32_t af[MT][4], bf[NT][2];
            #pragma unroll
            for (int mi = 0; mi < MT; mi++) {
                const int m0 = wrow * WM + mi * 16;
                af[mi][0] = f2tf32(As[kk + tg    ][m0 + g]);
                af[mi][1] = f2tf32(As[kk + tg    ][m0 + g + 8]);
                af[mi][2] = f2tf32(As[kk + tg + 4][m0 + g]);
                af[mi][3] = f2tf32(As[kk + tg + 4][m0 + g + 8]);
            }
            #pragma unroll
            for (int ni = 0; ni < NT; ni++) {
                const int n0 = wcol * WN + ni * 8 + g;
                bf[ni][0] = f2tf32(Bs[kk + tg    ][n0]);
                bf[ni][1] = f2tf32(Bs[kk + tg + 4][n0]);
            }
            #pragma unroll
            for (int mi = 0; mi < MT; mi++)
                #pragma unroll
                for (int ni = 0; ni < NT; ni++)
                    mma_tf32(acc[mi][ni], af[mi], bf[ni]);
        }
        __syncthreads();
    }

    // ---- epilogue ----
    #pragma unroll
    for (int mi = 0; mi < MT; mi++) {
        #pragma unroll
        for (int ni = 0; ni < NT; ni++) {
            const int row0 = cRow * BM + wrow * WM + mi * 16 + g;
            const int col0 = cCol * BN + wcol * WN + ni * 8 + 2 * tg;
            float c0 = acc[mi][ni][0];
            float c1 = acc[mi][ni][1];
            float c2 = acc[mi][ni][2];
            float c3 = acc[mi][ni][3];

            if (EPI == 1) {
                const float b0 = bias[col0], b1 = bias[col0 + 1];
                c0 += b0; c1 += b1; c2 += b0; c3 += b1;
            } else if (EPI == 2) {
                const float b0 = bias[col0], b1 = bias[col0 + 1];
                c0 += b0 + res[(long long)row0 * ldc + col0];
                c1 += b1 + res[(long long)row0 * ldc + col0 + 1];
                c2 += b0 + res[(long long)(row0 + 8) * ldc + col0];
                c3 += b1 + res[(long long)(row0 + 8) * ldc + col0 + 1];
            } else if (EPI == 3) {
                const float b0 = bias[col0], b1 = bias[col0 + 1];
                c0 += b0; c1 += b1; c2 += b0; c3 += b1;
                c0 = 0.5f * c0 * (1.0f + erff(c0 * 0.70710678118654752f));
                c1 = 0.5f * c1 * (1.0f + erff(c1 * 0.70710678118654752f));
                c2 = 0.5f * c2 * (1.0f + erff(c2 * 0.70710678118654752f));
                c3 = 0.5f * c3 * (1.0f + erff(c3 * 0.70710678118654752f));
            } else if (EPI == 4) {
                const float m0 = maskp[col0], m1 = maskp[col0 + 1];
                c0 = c0 * scale + m0;
                c1 = c1 * scale + m1;
                c2 = c2 * scale + m0;
                c3 = c3 * scale + m1;
            }

            *(float2*)&C[(long long)row0 * ldc + col0]       = make_float2(c0, c1);
            *(float2*)&C[(long long)(row0 + 8) * ldc + col0] = make_float2(c2, c3);
        }
    }
}

// ---------------------------------------------------------------------------
// Launch sequence
// ---------------------------------------------------------------------------
extern "C" void kernel_launch(void* const* d_in, const int* in_sizes, int n_in,
                              void* d_out, int out_size)
{
    const float* x    = (const float*)d_in[0];
    const float* mask = (const float*)d_in[1];
    const float* Wq   = (const float*)d_in[2];
    const float* bq   = (const float*)d_in[3];
    const float* Wk   = (const float*)d_in[4];
    const float* bk   = (const float*)d_in[5];
    const float* Wv   = (const float*)d_in[6];
    const float* bv   = (const float*)d_in[7];
    const float* Wo   = (const float*)d_in[8];
    const float* bo   = (const float*)d_in[9];
    const float* W1   = (const float*)d_in[10];
    const float* b1   = (const float*)d_in[11];
    const float* W2   = (const float*)d_in[12];
    const float* b2   = (const float*)d_in[13];
    const float* g1   = (const float*)d_in[14];
    const float* be1  = (const float*)d_in[15];
    const float* g2   = (const float*)d_in[16];
    const float* be2  = (const float*)d_in[17];
    float* out = (float*)d_out;

    float *h, *q, *kq, *vq, *sc, *o, *x1, *h2, *m1;
    cudaGetSymbolAddress((void**)&h,  g_h);
    cudaGetSymbolAddress((void**)&q,  g_q);
    cudaGetSymbolAddress((void**)&kq, g_k);
    cudaGetSymbolAddress((void**)&vq, g_v);
    cudaGetSymbolAddress((void**)&sc, g_sc);
    cudaGetSymbolAddress((void**)&o,  g_o);
    cudaGetSymbolAddress((void**)&x1, g_x1);
    cudaGetSymbolAddress((void**)&h2, g_h2);
    cudaGetSymbolAddress((void**)&m1, g_m1);

    // 1) h = LN(x; g1, be1)
    ln_kernel<<<MR, 256>>>(x, g1, be1, h);

    // 2) q = h @ Wq + bq          [4096 x 2048 x 2048]
    gemm_tc<128, 0, 1, 0><<<dim3(Hc / 128, MR / 128, 1), 256>>>(
        h, Hc, Wq, Hc, q, Hc, MR, Hc, Hc, bq, nullptr, nullptr, 0.f);

    // 3) k = h @ Wk + bk          [4096 x 512 x 2048]
    gemm_tc<128, 0, 1, 0><<<dim3(KVc / 128, MR / 128, 1), 256>>>(
        h, Hc, Wk, KVc, kq, KVc, MR, KVc, Hc, bk, nullptr, nullptr, 0.f);

    // 4) v = h @ Wv + bv
    gemm_tc<128, 0, 1, 0><<<dim3(KVc / 128, MR / 128, 1), 256>>>(
        h, Hc, Wv, KVc, vq, KVc, MR, KVc, Hc, bv, nullptr, nullptr, 0.f);

    // 5) scores[z] = (Q_z @ K_z^T) * 1/8 + mask     [64 x (2048 x 2048 x 64)]
    gemm_tc<128, 1, 4, 1><<<dim3(Sc / 128, Sc / 128, NHEADZ), 256>>>(
        q, Hc, kq, KVc, sc, Sc, Sc, Sc, Dc, nullptr, nullptr, mask, 0.125f);

    // 6) softmax rows
    softmax_kernel<<<(unsigned)((long long)NHEADZ * Sc), 256>>>(sc);

    // 7) o[z] = scores[z] @ V_z                      [64 x (2048 x 64 x 2048)]
    gemm_tc<64, 0, 0, 2><<<dim3(1, Sc / 128, NHEADZ), 256>>>(
        sc, Sc, vq, KVc, o, Hc, Sc, Dc, Sc, nullptr, nullptr, nullptr, 0.f);

    // 8) x1 = x + o @ Wo + bo
    gemm_tc<128, 0, 2, 0><<<dim3(Hc / 128, MR / 128, 1), 256>>>(
        o, Hc, Wo, Hc, x1, Hc, MR, Hc, Hc, bo, x, nullptr, 0.f);

    // 9) h2 = LN(x1; g2, be2)
    ln_kernel<<<MR, 256>>>(x1, g2, be2, h2);

    // 10) m1 = gelu(h2 @ W1 + b1)   [4096 x 8192 x 2048]
    gemm_tc<128, 0, 3, 0><<<dim3(FFc / 128, MR / 128, 1), 256>>>(
        h2, Hc, W1, FFc, m1, FFc, MR, FFc, Hc, b1, nullptr, nullptr, 0.f);

    // 11) out = x1 + m1 @ W2 + b2   [4096 x 2048 x 8192]
    gemm_tc<128, 0, 2, 0><<<dim3(Hc / 128, MR / 128, 1), 256>>>(
        m1, FFc, W2, Hc, out, Hc, MR, Hc, FFc, b2, x1, nullptr, 0.f);
}

// round 3
// speedup vs baseline: 3.0446x; 1.1660x over previous
#include <cuda_runtime.h>
#include <math.h>
#include <stdint.h>

// ---------------------------------------------------------------------------
// Problem constants (fixed shapes)
// ---------------------------------------------------------------------------
constexpr int Bc   = 2;
constexpr int Sc   = 2048;
constexpr int Hc   = 2048;
constexpr int KVHc = 8;
constexpr int QPKc = 4;
constexpr int Dc   = 64;
constexpr int KVc  = 512;    // KVH * D
constexpr int FFc  = 8192;
constexpr int MR   = Bc * Sc;            // 4096 rows
constexpr int NHEADZ = Bc * KVHc * QPKc; // 64 head instances

// ---------------------------------------------------------------------------
// Scratch (device globals; no runtime allocation allowed)
// ---------------------------------------------------------------------------
__device__ float g_h  [(size_t)MR * Hc];
__device__ float g_q  [(size_t)MR * Hc];
__device__ float g_k  [(size_t)MR * KVc];
__device__ float g_v  [(size_t)MR * KVc];
__device__ float g_o  [(size_t)MR * Hc];
__device__ float g_x1 [(size_t)MR * Hc];
__device__ float g_h2 [(size_t)MR * Hc];
__device__ float g_m1 [(size_t)MR * FFc];

// ---------------------------------------------------------------------------
// Helpers
// ---------------------------------------------------------------------------
__device__ __forceinline__ uint32_t f2tf32(float f) {
    uint32_t u;
    asm("cvt.rna.tf32.f32 %0, %1;" : "=r"(u) : "f"(f));
    return u;
}

__device__ __forceinline__ void mma_tf32(float* c, const uint32_t* a, const uint32_t* b) {
    asm volatile(
        "mma.sync.aligned.m16n8k8.row.col.f32.tf32.tf32.f32 "
        "{%0,%1,%2,%3}, {%4,%5,%6,%7}, {%8,%9}, {%0,%1,%2,%3};\n"
        : "+f"(c[0]), "+f"(c[1]), "+f"(c[2]), "+f"(c[3])
        : "r"(a[0]), "r"(a[1]), "r"(a[2]), "r"(a[3]),
          "r"(b[0]), "r"(b[1]));
}

// FFMA-only exp (MUFU is the bottleneck at 2.7e8 evals).
// x <= 0 expected. 2^y with magic rounding + deg-5 poly; rel err ~3e-6.
__device__ __forceinline__ float fast_exp(float x) {
    float y = x * 1.4426950408889634f;
    y = fmaxf(y, -126.0f);
    float z = y + 12582912.0f;                 // round-to-nearest int
    int   n = __float_as_int(z) - 0x4B400000;
    float f = y - (z - 12582912.0f);           // f in [-0.5, 0.5]
    float p =             1.3333558146428443e-3f;
    p = fmaf(p, f,        9.6181291076284772e-3f);
    p = fmaf(p, f,        5.5504108664821580e-2f);
    p = fmaf(p, f,        2.4022650695910072e-1f);
    p = fmaf(p, f,        6.9314718055994531e-1f);
    p = fmaf(p, f,        1.0f);
    return p * __int_as_float((n + 127) << 23);
}

__device__ __forceinline__ void cp_async16(uint32_t dst, const void* src) {
    asm volatile("cp.async.cg.shared.global [%0], [%1], 16;" :: "r"(dst), "l"(src));
}
#define CP_COMMIT()  asm volatile("cp.async.commit_group;\n" ::: "memory")
#define CP_WAIT(N)   asm volatile("cp.async.wait_group %0;\n" :: "n"(N) : "memory")

// ---------------------------------------------------------------------------
// LayerNorm
// ---------------------------------------------------------------------------
__global__ void ln_kernel(const float* __restrict__ x,
                          const float* __restrict__ g,
                          const float* __restrict__ b,
                          float* __restrict__ out)
{
    const int HD = Hc;
    const long long row = blockIdx.x;
    const float* xr = x + row * HD;
    float* outr = out + row * HD;
    const int tid = threadIdx.x;

    float4 v0 = *(const float4*)(xr + tid * 8);
    float4 v1 = *(const float4*)(xr + tid * 8 + 4);
    float s  = v0.x + v0.y + v0.z + v0.w + v1.x + v1.y + v1.z + v1.w;
    float sq = v0.x*v0.x + v0.y*v0.y + v0.z*v0.z + v0.w*v0.w
             + v1.x*v1.x + v1.y*v1.y + v1.z*v1.z + v1.w*v1.w;

    #pragma unroll
    for (int o = 16; o; o >>= 1) {
        s  += __shfl_xor_sync(0xffffffffu, s,  o);
        sq += __shfl_xor_sync(0xffffffffu, sq, o);
    }
    __shared__ float ss[8], ssq[8];
    if ((tid & 31) == 0) { ss[tid >> 5] = s; ssq[tid >> 5] = sq; }
    __syncthreads();
    float ts = 0.f, tsq = 0.f;
    #pragma unroll
    for (int i = 0; i < 8; i++) { ts += ss[i]; tsq += ssq[i]; }

    const float mu  = ts * (1.0f / HD);
    const float var = tsq * (1.0f / HD) - mu * mu;
    const float inv = rsqrtf(var + 1e-5f);

    float4 gg0 = *(const float4*)(g + tid * 8);
    float4 gg1 = *(const float4*)(g + tid * 8 + 4);
    float4 bb0 = *(const float4*)(b + tid * 8);
    float4 bb1 = *(const float4*)(b + tid * 8 + 4);

    float4 o0, o1;
    o0.x = (v0.x - mu) * inv * gg0.x + bb0.x;
    o0.y = (v0.y - mu) * inv * gg0.y + bb0.y;
    o0.z = (v0.z - mu) * inv * gg0.z + bb0.z;
    o0.w = (v0.w - mu) * inv * gg0.w + bb0.w;
    o1.x = (v1.x - mu) * inv * gg1.x + bb1.x;
    o1.y = (v1.y - mu) * inv * gg1.y + bb1.y;
    o1.z = (v1.z - mu) * inv * gg1.z + bb1.z;
    o1.w = (v1.w - mu) * inv * gg1.w + bb1.w;
    *(float4*)(outr + tid * 8)     = o0;
    *(float4*)(outr + tid * 8 + 4) = o1;
}

// ---------------------------------------------------------------------------
// tf32 tensor-core GEMM (projections + FFN). Same as round 2.
// ---------------------------------------------------------------------------
template<int BN, int TRANSB, int EPI>
__global__ __launch_bounds__(256)
void gemm_tc(const float* __restrict__ A, int lda,
             const float* __restrict__ Bm, int ldb,
             float* __restrict__ C, int ldc,
             int M, int N, int K,
             const float* __restrict__ bias,
             const float* __restrict__ res)
{
    constexpr int BM = 128, BK = 16;
    constexpr int WM = (BN == 128) ? 64 : 32;
    constexpr int WN = 32;
    constexpr int MT = WM / 16;
    constexpr int NT = WN / 8;

    __shared__ float As[BK][BM + 8];
    __shared__ float Bs[BK][BN + 8];

    const int tid  = threadIdx.x;
    const int warp = tid >> 5;
    const int lane = tid & 31;
    const int g    = lane >> 2;
    const int tg   = lane & 3;
    const int wrow = (BN == 128) ? (warp >> 2) : (warp >> 1);
    const int wcol = (BN == 128) ? (warp & 3)  : (warp & 1);

    const int cRow = blockIdx.y;
    const int cCol = blockIdx.x;

    float acc[MT][NT][4];
    #pragma unroll
    for (int mi = 0; mi < MT; mi++)
        #pragma unroll
        for (int ni = 0; ni < NT; ni++)
            #pragma unroll
            for (int r = 0; r < 4; r++) acc[mi][ni][r] = 0.f;

    constexpr int ACH = 2;
    constexpr int BCH = (TRANSB == 1) ? 2 : (BN == 128 ? 2 : 1);
    float4 pa[ACH], pb[BCH];

    const int ntiles = K / BK;

    #pragma unroll
    for (int c = 0; c < ACH; c++) {
        int flat = c * 256 + tid;
        int r = flat >> 2, qq = flat & 3;
        pa[c] = *(const float4*)(A + (long long)(cRow * BM + r) * lda + qq * 4);
    }
    #pragma unroll
    for (int c = 0; c < BCH; c++) {
        int flat = c * 256 + tid;
        if (TRANSB == 1) {
            int n = flat >> 2, qq = flat & 3;
            pb[c] = *(const float4*)(Bm + (long long)(cCol * BN + n) * ldb + qq * 4);
        } else if (BN == 128) {
            int k = flat >> 5, qq = flat & 31;
            pb[c] = *(const float4*)(Bm + (long long)k * ldb + cCol * BN + qq * 4);
        } else {
            int k = flat >> 4, qq = flat & 15;
            pb[c] = *(const float4*)(Bm + (long long)k * ldb + cCol * BN + qq * 4);
        }
    }

    for (int kt = 0; kt < ntiles; ++kt) {
        #pragma unroll
        for (int c = 0; c < ACH; c++) {
            int flat = c * 256 + tid;
            int r = flat >> 2, qq = flat & 3;
            As[qq * 4 + 0][r] = pa[c].x;
            As[qq * 4 + 1][r] = pa[c].y;
            As[qq * 4 + 2][r] = pa[c].z;
            As[qq * 4 + 3][r] = pa[c].w;
        }
        #pragma unroll
        for (int c = 0; c < BCH; c++) {
            int flat = c * 256 + tid;
            if (TRANSB == 1) {
                int n = flat >> 2, qq = flat & 3;
                Bs[qq * 4 + 0][n] = pb[c].x;
                Bs[qq * 4 + 1][n] = pb[c].y;
                Bs[qq * 4 + 2][n] = pb[c].z;
                Bs[qq * 4 + 3][n] = pb[c].w;
            } else if (BN == 128) {
                int k = flat >> 5, qq = flat & 31;
                *(float4*)&Bs[k][qq * 4] = pb[c];
            } else {
                int k = flat >> 4, qq = flat & 15;
                *(float4*)&Bs[k][qq * 4] = pb[c];
            }
        }
        __syncthreads();

        if (kt + 1 < ntiles) {
            const int k0 = (kt + 1) * BK;
            #pragma unroll
            for (int c = 0; c < ACH; c++) {
                int flat = c * 256 + tid;
                int r = flat >> 2, qq = flat & 3;
                pa[c] = *(const float4*)(A + (long long)(cRow * BM + r) * lda + k0 + qq * 4);
            }
            #pragma unroll
            for (int c = 0; c < BCH; c++) {
                int flat = c * 256 + tid;
                if (TRANSB == 1) {
                    int n = flat >> 2, qq = flat & 3;
                    pb[c] = *(const float4*)(Bm + (long long)(cCol * BN + n) * ldb + k0 + qq * 4);
                } else if (BN == 128) {
                    int k = flat >> 5, qq = flat & 31;
                    pb[c] = *(const float4*)(Bm + (long long)(k0 + k) * ldb + cCol * BN + qq * 4);
                } else {
                    int k = flat >> 4, qq = flat & 15;
                    pb[c] = *(const float4*)(Bm + (long long)(k0 + k) * ldb + cCol * BN + qq * 4);
                }
            }
        }

        #pragma unroll
        for (int kk = 0; kk < BK; kk += 8) {
            uint32_t af[MT][4], bf[NT][2];
            #pragma unroll
            for (int mi = 0; mi < MT; mi++) {
                const int mm0 = wrow * WM + mi * 16;
                af[mi][0] = f2tf32(As[kk + tg    ][mm0 + g]);
                af[mi][1] = f2tf32(As[kk + tg    ][mm0 + g + 8]);
                af[mi][2] = f2tf32(As[kk + tg + 4][mm0 + g]);
                af[mi][3] = f2tf32(As[kk + tg + 4][mm0 + g + 8]);
            }
            #pragma unroll
            for (int ni = 0; ni < NT; ni++) {
                const int n0 = wcol * WN + ni * 8 + g;
                bf[ni][0] = f2tf32(Bs[kk + tg    ][n0]);
                bf[ni][1] = f2tf32(Bs[kk + tg + 4][n0]);
            }
            #pragma unroll
            for (int mi = 0; mi < MT; mi++)
                #pragma unroll
                for (int ni = 0; ni < NT; ni++)
                    mma_tf32(acc[mi][ni], af[mi], bf[ni]);
        }
        __syncthreads();
    }

    #pragma unroll
    for (int mi = 0; mi < MT; mi++) {
        #pragma unroll
        for (int ni = 0; ni < NT; ni++) {
            const int row0 = cRow * BM + wrow * WM + mi * 16 + g;
            const int col0 = cCol * BN + wcol * WN + ni * 8 + 2 * tg;
            float c0 = acc[mi][ni][0];
            float c1 = acc[mi][ni][1];
            float c2 = acc[mi][ni][2];
            float c3 = acc[mi][ni][3];

            if (EPI == 1) {
                const float b0 = bias[col0], b1 = bias[col0 + 1];
                c0 += b0; c1 += b1; c2 += b0; c3 += b1;
            } else if (EPI == 2) {
                const float b0 = bias[col0], b1 = bias[col0 + 1];
                c0 += b0 + res[(long long)row0 * ldc + col0];
                c1 += b1 + res[(long long)row0 * ldc + col0 + 1];
                c2 += b0 + res[(long long)(row0 + 8) * ldc + col0];
                c3 += b1 + res[(long long)(row0 + 8) * ldc + col0 + 1];
            } else if (EPI == 3) {
                const float b0 = bias[col0], b1 = bias[col0 + 1];
                c0 += b0; c1 += b1; c2 += b0; c3 += b1;
                c0 = 0.5f * c0 * (1.0f + erff(c0 * 0.70710678118654752f));
                c1 = 0.5f * c1 * (1.0f + erff(c1 * 0.70710678118654752f));
                c2 = 0.5f * c2 * (1.0f + erff(c2 * 0.70710678118654752f));
                c3 = 0.5f * c3 * (1.0f + erff(c3 * 0.70710678118654752f));
            }

            *(float2*)&C[(long long)row0 * ldc + col0]       = make_float2(c0, c1);
            *(float2*)&C[(long long)(row0 + 8) * ldc + col0] = make_float2(c2, c3);
        }
    }
}

// ---------------------------------------------------------------------------
// Flash attention: one CTA = (head-instance z, 128-query tile).
// 256 threads / 8 warps; warp w owns query rows 16w..16w+15 end-to-end.
// Online softmax with fast_exp; K/V streamed via cp.async (phase-shifted
// single buffers); P round-trips through smem warp-locally as tf32 bits.
// ---------------------------------------------------------------------------
constexpr int FA_LD  = 68;    // padded row (floats) for Q/K/V tiles
constexpr int PS_LD  = 132;   // padded row for P
constexpr int SMW_Q  = 0;
constexpr int SMW_K  = 128 * FA_LD;          // 8704
constexpr int SMW_V  = 2 * 128 * FA_LD;      // 17408
constexpr int SMW_P  = 3 * 128 * FA_LD;      // 26112
constexpr int FA_SMEM_BYTES = (SMW_P + 128 * PS_LD) * 4;  // 172032

__global__ __launch_bounds__(256, 1)
void flash_kernel(const float* __restrict__ Qg, const float* __restrict__ Kg,
                  const float* __restrict__ Vg, const float* __restrict__ maskg,
                  float* __restrict__ Og)
{
    extern __shared__ float sm[];
    float*    Qs  = sm + SMW_Q;                 // tf32 bits
    float*    Ks  = sm + SMW_K;                 // raw fp32
    float*    Vs  = sm + SMW_V;                 // raw fp32
    uint32_t* Psu = (uint32_t*)(sm + SMW_P);    // tf32 bits
    uint32_t* Qsu = (uint32_t*)Qs;

    const int tid  = threadIdx.x;
    const int warp = tid >> 5;
    const int lane = tid & 31;
    const int g    = lane >> 2;
    const int tg   = lane & 3;
    const int qt   = blockIdx.x;   // 0..15
    const int z    = blockIdx.y;   // 0..63
    const int bi   = z >> 5, kvh = (z >> 2) & 7, qpk = z & 3;
    const int m0   = warp * 16;

    const float* Qh = Qg + (size_t)bi * Sc * Hc + (size_t)(qt * 128) * Hc
                    + kvh * (QPKc * Dc) + qpk * Dc;
    const float* Kh = Kg + (size_t)bi * Sc * KVc + kvh * Dc;
    const float* Vh = Vg + (size_t)bi * Sc * KVc + kvh * Dc;
    float*       Oh = Og + (size_t)bi * Sc * Hc + (size_t)(qt * 128) * Hc
                    + (kvh * QPKc + qpk) * Dc;
    const float* maskp = maskg + (size_t)bi * Sc;

    // ---- load Q tile (convert to tf32 once) ----
    #pragma unroll
    for (int c = 0; c < 8; c++) {
        int flat = c * 256 + tid, row = flat >> 4, c4 = (flat & 15) * 4;
        float4 qv = *(const float4*)(Qh + (size_t)row * Hc + c4);
        uint32_t* d = Qsu + row * FA_LD + c4;
        d[0] = f2tf32(qv.x); d[1] = f2tf32(qv.y);
        d[2] = f2tf32(qv.z); d[3] = f2tf32(qv.w);
    }

    const uint32_t ks_b = (uint32_t)__cvta_generic_to_shared(Ks);
    const uint32_t vs_b = (uint32_t)__cvta_generic_to_shared(Vs);

    // ---- prologue: async K0, V0 ----
    #pragma unroll
    for (int c = 0; c < 8; c++) {
        int flat = c * 256 + tid, key = flat >> 4, c4 = (flat & 15) * 4;
        cp_async16(ks_b + (key * FA_LD + c4) * 4, Kh + (size_t)key * KVc + c4);
    }
    CP_COMMIT();
    #pragma unroll
    for (int c = 0; c < 8; c++) {
        int flat = c * 256 + tid, key = flat >> 4, c4 = (flat & 15) * 4;
        cp_async16(vs_b + (key * FA_LD + c4) * 4, Vh + (size_t)key * KVc + c4);
    }
    CP_COMMIT();
    CP_WAIT(1);           // K0 arrived (V0 may fly)
    __syncthreads();

    float oacc[8][4];
    #pragma unroll
    for (int ni = 0; ni < 8; ni++)
        #pragma unroll
        for (int r = 0; r < 4; r++) oacc[ni][r] = 0.f;
    float m_lo = -1e30f, m_hi = -1e30f, l_lo = 0.f, l_hi = 0.f;

    for (int t = 0; t < 16; t++) {
        // ================= QK^T (S = Q @ K^T, rows m0.., all 128 keys) ======
        float sacc[16][4];
        #pragma unroll
        for (int ni = 0; ni < 16; ni++)
            #pragma unroll
            for (int r = 0; r < 4; r++) sacc[ni][r] = 0.f;

        #pragma unroll
        for (int kk = 0; kk < 64; kk += 8) {
            uint32_t af[4];
            af[0] = Qsu[(m0 + g)     * FA_LD + kk + tg];
            af[1] = Qsu[(m0 + g + 8) * FA_LD + kk + tg];
            af[2] = Qsu[(m0 + g)     * FA_LD + kk + tg + 4];
            af[3] = Qsu[(m0 + g + 8) * FA_LD + kk + tg + 4];
            #pragma unroll
            for (int ni = 0; ni < 16; ni++) {
                uint32_t bf[2];
                bf[0] = __float_as_uint(Ks[(ni * 8 + g) * FA_LD + kk + tg]);
                bf[1] = __float_as_uint(Ks[(ni * 8 + g) * FA_LD + kk + tg + 4]);
                mma_tf32(sacc[ni], af, bf);
            }
        }
        __syncthreads();                       // everyone done reading Ks

        if (t < 15) {                          // stream next K tile
            const float* Kn = Kh + (size_t)(t + 1) * 128 * KVc;
            #pragma unroll
            for (int c = 0; c < 8; c++) {
                int flat = c * 256 + tid, key = flat >> 4, c4 = (flat & 15) * 4;
                cp_async16(ks_b + (key * FA_LD + c4) * 4, Kn + (size_t)key * KVc + c4);
            }
            CP_COMMIT();
        }

        // ================= online softmax (registers + warp shuffles) ======
        const int k0t = t * 128;
        float mloc_lo = -1e30f, mloc_hi = -1e30f;
        #pragma unroll
        for (int ni = 0; ni < 16; ni++) {
            float2 mk = *(const float2*)(maskp + k0t + ni * 8 + 2 * tg);
            float s0 = fmaf(sacc[ni][0], 0.125f, mk.x);
            float s1 = fmaf(sacc[ni][1], 0.125f, mk.y);
            float s2 = fmaf(sacc[ni][2], 0.125f, mk.x);
            float s3 = fmaf(sacc[ni][3], 0.125f, mk.y);
            sacc[ni][0] = s0; sacc[ni][1] = s1; sacc[ni][2] = s2; sacc[ni][3] = s3;
            mloc_lo = fmaxf(mloc_lo, fmaxf(s0, s1));
            mloc_hi = fmaxf(mloc_hi, fmaxf(s2, s3));
        }
        mloc_lo = fmaxf(mloc_lo, __shfl_xor_sync(0xffffffffu, mloc_lo, 1));
        mloc_lo = fmaxf(mloc_lo, __shfl_xor_sync(0xffffffffu, mloc_lo, 2));
        mloc_hi = fmaxf(mloc_hi, __shfl_xor_sync(0xffffffffu, mloc_hi, 1));
        mloc_hi = fmaxf(mloc_hi, __shfl_xor_sync(0xffffffffu, mloc_hi, 2));

        const float mnew_lo = fmaxf(m_lo, mloc_lo);
        const float mnew_hi = fmaxf(m_hi, mloc_hi);
        const float alpha_lo = fast_exp(m_lo - mnew_lo);
        const float alpha_hi = fast_exp(m_hi - mnew_hi);
        m_lo = mnew_lo; m_hi = mnew_hi;

        float rs_lo = 0.f, rs_hi = 0.f;
        #pragma unroll
        for (int ni = 0; ni < 16; ni++) {
            float p0 = fast_exp(sacc[ni][0] - mnew_lo);
            float p1 = fast_exp(sacc[ni][1] - mnew_lo);
            float p2 = fast_exp(sacc[ni][2] - mnew_hi);
            float p3 = fast_exp(sacc[ni][3] - mnew_hi);
            rs_lo += p0 + p1; rs_hi += p2 + p3;
            uint2 plo = make_uint2(f2tf32(p0), f2tf32(p1));
            uint2 phi = make_uint2(f2tf32(p2), f2tf32(p3));
            *(uint2*)&Psu[(m0 + g)     * PS_LD + ni * 8 + 2 * tg] = plo;
            *(uint2*)&Psu[(m0 + g + 8) * PS_LD + ni * 8 + 2 * tg] = phi;
        }
        rs_lo += __shfl_xor_sync(0xffffffffu, rs_lo, 1);
        rs_lo += __shfl_xor_sync(0xffffffffu, rs_lo, 2);
        rs_hi += __shfl_xor_sync(0xffffffffu, rs_hi, 1);
        rs_hi += __shfl_xor_sync(0xffffffffu, rs_hi, 2);
        l_lo = fmaf(l_lo, alpha_lo, rs_lo);
        l_hi = fmaf(l_hi, alpha_hi, rs_hi);

        #pragma unroll
        for (int ni = 0; ni < 8; ni++) {
            oacc[ni][0] *= alpha_lo; oacc[ni][1] *= alpha_lo;
            oacc[ni][2] *= alpha_hi; oacc[ni][3] *= alpha_hi;
        }

        // wait V_t everywhere (K_{t+1} may still fly)
        if (t < 15) { CP_WAIT(1); } else { CP_WAIT(0); }
        __syncthreads();

        // ================= PV: O += P @ V ==================================
        #pragma unroll
        for (int kk = 0; kk < 16; kk++) {
            uint32_t af[4];
            af[0] = Psu[(m0 + g)     * PS_LD + kk * 8 + tg];
            af[1] = Psu[(m0 + g + 8) * PS_LD + kk * 8 + tg];
            af[2] = Psu[(m0 + g)     * PS_LD + kk * 8 + tg + 4];
            af[3] = Psu[(m0 + g + 8) * PS_LD + kk * 8 + tg + 4];
            #pragma unroll
            for (int ni = 0; ni < 8; ni++) {
                uint32_t bf[2];
                bf[0] = __float_as_uint(Vs[(kk * 8 + tg)     * FA_LD + ni * 8 + g]);
                bf[1] = __float_as_uint(Vs[(kk * 8 + tg + 4) * FA_LD + ni * 8 + g]);
                mma_tf32(oacc[ni], af, bf);
            }
        }
        __syncthreads();                       // everyone done reading Vs

        if (t < 15) {                          // stream next V tile
            const float* Vn = Vh + (size_t)(t + 1) * 128 * KVc;
            #pragma unroll
            for (int c = 0; c < 8; c++) {
                int flat = c * 256 + tid, key = flat >> 4, c4 = (flat & 15) * 4;
                cp_async16(vs_b + (key * FA_LD + c4) * 4, Vn + (size_t)key * KVc + c4);
            }
            CP_COMMIT();
            CP_WAIT(1);                        // K_{t+1} arrived
            __syncthreads();
        }
    }

    // ---- finalize ----
    const float inv_lo = 1.0f / l_lo;
    const float inv_hi = 1.0f / l_hi;
    #pragma unroll
    for (int ni = 0; ni < 8; ni++) {
        const int col = ni * 8 + 2 * tg;
        *(float2*)(Oh + (size_t)(m0 + g)     * Hc + col) =
            make_float2(oacc[ni][0] * inv_lo, oacc[ni][1] * inv_lo);
        *(float2*)(Oh + (size_t)(m0 + g + 8) * Hc + col) =
            make_float2(oacc[ni][2] * inv_hi, oacc[ni][3] * inv_hi);
    }
}

// ---------------------------------------------------------------------------
// Launch sequence
// ---------------------------------------------------------------------------
extern "C" void kernel_launch(void* const* d_in, const int* in_sizes, int n_in,
                              void* d_out, int out_size)
{
    const float* x    = (const float*)d_in[0];
    const float* mask = (const float*)d_in[1];
    const float* Wq   = (const float*)d_in[2];
    const float* bq   = (const float*)d_in[3];
    const float* Wk   = (const float*)d_in[4];
    const float* bk   = (const float*)d_in[5];
    const float* Wv   = (const float*)d_in[6];
    const float* bv   = (const float*)d_in[7];
    const float* Wo   = (const float*)d_in[8];
    const float* bo   = (const float*)d_in[9];
    const float* W1   = (const float*)d_in[10];
    const float* b1   = (const float*)d_in[11];
    const float* W2   = (const float*)d_in[12];
    const float* b2   = (const float*)d_in[13];
    const float* g1   = (const float*)d_in[14];
    const float* be1  = (const float*)d_in[15];
    const float* g2   = (const float*)d_in[16];
    const float* be2  = (const float*)d_in[17];
    float* out = (float*)d_out;

    float *h, *q, *kq, *vq, *o, *x1, *h2, *m1;
    cudaGetSymbolAddress((void**)&h,  g_h);
    cudaGetSymbolAddress((void**)&q,  g_q);
    cudaGetSymbolAddress((void**)&kq, g_k);
    cudaGetSymbolAddress((void**)&vq, g_v);
    cudaGetSymbolAddress((void**)&o,  g_o);
    cudaGetSymbolAddress((void**)&x1, g_x1);
    cudaGetSymbolAddress((void**)&h2, g_h2);
    cudaGetSymbolAddress((void**)&m1, g_m1);

    static bool attr_done = false;
    if (!attr_done) {
        cudaFuncSetAttribute(flash_kernel,
                             cudaFuncAttributeMaxDynamicSharedMemorySize,
                             FA_SMEM_BYTES);
        attr_done = true;
    }

    // 1) h = LN(x)
    ln_kernel<<<MR, 256>>>(x, g1, be1, h);

    // 2-4) Q,K,V projections
    gemm_tc<128, 0, 1><<<dim3(Hc / 128, MR / 128), 256>>>(
        h, Hc, Wq, Hc, q, Hc, MR, Hc, Hc, bq, nullptr);
    gemm_tc<128, 0, 1><<<dim3(KVc / 128, MR / 128), 256>>>(
        h, Hc, Wk, KVc, kq, KVc, MR, KVc, Hc, bk, nullptr);
    gemm_tc<128, 0, 1><<<dim3(KVc / 128, MR / 128), 256>>>(
        h, Hc, Wv, KVc, vq, KVc, MR, KVc, Hc, bv, nullptr);

    // 5) fused flash attention -> o
    flash_kernel<<<dim3(16, NHEADZ), 256, FA_SMEM_BYTES>>>(q, kq, vq, mask, o);

    // 6) x1 = x + o @ Wo + bo
    gemm_tc<128, 0, 2><<<dim3(Hc / 128, MR / 128), 256>>>(
        o, Hc, Wo, Hc, x1, Hc, MR, Hc, Hc, bo, x);

    // 7) h2 = LN(x1)
    ln_kernel<<<MR, 256>>>(x1, g2, be2, h2);

    // 8) m1 = gelu(h2 @ W1 + b1)
    gemm_tc<128, 0, 3><<<dim3(FFc / 128, MR / 128), 256>>>(
        h2, Hc, W1, FFc, m1, FFc, MR, FFc, Hc, b1, nullptr);

    // 9) out = x1 + m1 @ W2 + b2
    gemm_tc<128, 0, 2><<<dim3(Hc / 128, MR / 128), 256>>>(
        m1, FFc, W2, Hc, out, Hc, MR, Hc, FFc, b2, x1);
}

// round 5
// speedup vs baseline: 3.1823x; 1.0452x over previous
#include <cuda_runtime.h>
#include <math.h>
#include <stdint.h>

// ---------------------------------------------------------------------------
// Problem constants (fixed shapes)
// ---------------------------------------------------------------------------
constexpr int Bc   = 2;
constexpr int Sc   = 2048;
constexpr int Hc   = 2048;
constexpr int KVHc = 8;
constexpr int QPKc = 4;
constexpr int Dc   = 64;
constexpr int KVc  = 512;    // KVH * D
constexpr int FFc  = 8192;
constexpr int MR   = Bc * Sc;            // 4096 rows
constexpr int NHEADZ = Bc * KVHc * QPKc; // 64 head instances

// ---------------------------------------------------------------------------
// Scratch (device globals; no runtime allocation allowed)
// ---------------------------------------------------------------------------
__device__ float g_h  [(size_t)MR * Hc];
__device__ float g_q  [(size_t)MR * Hc];
__device__ float g_k  [(size_t)MR * KVc];
__device__ float g_v  [(size_t)MR * KVc];
__device__ float g_o  [(size_t)MR * Hc];
__device__ float g_x1 [(size_t)MR * Hc];
__device__ float g_h2 [(size_t)MR * Hc];
__device__ float g_m1 [(size_t)MR * FFc];

// ---------------------------------------------------------------------------
// Helpers
// ---------------------------------------------------------------------------
__device__ __forceinline__ uint32_t f2tf32(float f) {
    uint32_t u;
    asm("cvt.rna.tf32.f32 %0, %1;" : "=r"(u) : "f"(f));
    return u;
}

__device__ __forceinline__ void mma_tf32(float* c, const uint32_t* a, const uint32_t* b) {
    asm volatile(
        "mma.sync.aligned.m16n8k8.row.col.f32.tf32.tf32.f32 "
        "{%0,%1,%2,%3}, {%4,%5,%6,%7}, {%8,%9}, {%0,%1,%2,%3};\n"
        : "+f"(c[0]), "+f"(c[1]), "+f"(c[2]), "+f"(c[3])
        : "r"(a[0]), "r"(a[1]), "r"(a[2]), "r"(a[3]),
          "r"(b[0]), "r"(b[1]));
}

// FFMA-only exp; x <= 0 expected. rel err ~3e-6.
__device__ __forceinline__ float fast_exp(float x) {
    float y = x * 1.4426950408889634f;
    y = fmaxf(y, -126.0f);
    float z = y + 12582912.0f;
    int   n = __float_as_int(z) - 0x4B400000;
    float f = y - (z - 12582912.0f);
    float p =             1.3333558146428443e-3f;
    p = fmaf(p, f,        9.6181291076284772e-3f);
    p = fmaf(p, f,        5.5504108664821580e-2f);
    p = fmaf(p, f,        2.4022650695910072e-1f);
    p = fmaf(p, f,        6.9314718055994531e-1f);
    p = fmaf(p, f,        1.0f);
    return p * __int_as_float((n + 127) << 23);
}

__device__ __forceinline__ void cp_async16(uint32_t dst, const void* src) {
    asm volatile("cp.async.cg.shared.global [%0], [%1], 16;" :: "r"(dst), "l"(src));
}
#define CP_COMMIT()  asm volatile("cp.async.commit_group;\n" ::: "memory")
#define CP_WAIT(N)   asm volatile("cp.async.wait_group %0;\n" :: "n"(N) : "memory")

// ---------------------------------------------------------------------------
// LayerNorm
// ---------------------------------------------------------------------------
__global__ void ln_kernel(const float* __restrict__ x,
                          const float* __restrict__ g,
                          const float* __restrict__ b,
                          float* __restrict__ out)
{
    const int HD = Hc;
    const long long row = blockIdx.x;
    const float* xr = x + row * HD;
    float* outr = out + row * HD;
    const int tid = threadIdx.x;

    float4 v0 = *(const float4*)(xr + tid * 8);
    float4 v1 = *(const float4*)(xr + tid * 8 + 4);
    float s  = v0.x + v0.y + v0.z + v0.w + v1.x + v1.y + v1.z + v1.w;
    float sq = v0.x*v0.x + v0.y*v0.y + v0.z*v0.z + v0.w*v0.w
             + v1.x*v1.x + v1.y*v1.y + v1.z*v1.z + v1.w*v1.w;

    #pragma unroll
    for (int o = 16; o; o >>= 1) {
        s  += __shfl_xor_sync(0xffffffffu, s,  o);
        sq += __shfl_xor_sync(0xffffffffu, sq, o);
    }
    __shared__ float ss[8], ssq[8];
    if ((tid & 31) == 0) { ss[tid >> 5] = s; ssq[tid >> 5] = sq; }
    __syncthreads();
    float ts = 0.f, tsq = 0.f;
    #pragma unroll
    for (int i = 0; i < 8; i++) { ts += ss[i]; tsq += ssq[i]; }

    const float mu  = ts * (1.0f / HD);
    const float var = tsq * (1.0f / HD) - mu * mu;
    const float inv = rsqrtf(var + 1e-5f);

    float4 gg0 = *(const float4*)(g + tid * 8);
    float4 gg1 = *(const float4*)(g + tid * 8 + 4);
    float4 bb0 = *(const float4*)(b + tid * 8);
    float4 bb1 = *(const float4*)(b + tid * 8 + 4);

    float4 o0, o1;
    o0.x = (v0.x - mu) * inv * gg0.x + bb0.x;
    o0.y = (v0.y - mu) * inv * gg0.y + bb0.y;
    o0.z = (v0.z - mu) * inv * gg0.z + bb0.z;
    o0.w = (v0.w - mu) * inv * gg0.w + bb0.w;
    o1.x = (v1.x - mu) * inv * gg1.x + bb1.x;
    o1.y = (v1.y - mu) * inv * gg1.y + bb1.y;
    o1.z = (v1.z - mu) * inv * gg1.z + bb1.z;
    o1.w = (v1.w - mu) * inv * gg1.w + bb1.w;
    *(float4*)(outr + tid * 8)     = o0;
    *(float4*)(outr + tid * 8 + 4) = o1;
}

// ---------------------------------------------------------------------------
// tf32 tensor-core GEMM (projections + FFN).
//   KVSEL=1: grid.x doubled; second half uses Bm2/bias2/C2 (fused K+V proj).
// ---------------------------------------------------------------------------
template<int BN, int TRANSB, int EPI, int KVSEL>
__global__ __launch_bounds__(256)
void gemm_tc(const float* __restrict__ A, int lda,
             const float* __restrict__ Bm, int ldb,
             float* __restrict__ C, int ldc,
             int M, int N, int K,
             const float* __restrict__ bias,
             const float* __restrict__ res,
             const float* __restrict__ Bm2,
             const float* __restrict__ bias2,
             float* __restrict__ C2)
{
    constexpr int BM = 128, BK = 16;
    constexpr int WM = (BN == 128) ? 64 : 32;
    constexpr int WN = 32;
    constexpr int MT = WM / 16;
    constexpr int NT = WN / 8;

    __shared__ float As[BK][BM + 8];
    __shared__ float Bs[BK][BN + 8];

    const int tid  = threadIdx.x;
    const int warp = tid >> 5;
    const int lane = tid & 31;
    const int g    = lane >> 2;
    const int tg   = lane & 3;
    const int wrow = (BN == 128) ? (warp >> 2) : (warp >> 1);
    const int wcol = (BN == 128) ? (warp & 3)  : (warp & 1);

    const int cRow = blockIdx.y;
    int cCol = blockIdx.x;
    if (KVSEL) {
        const int half = gridDim.x >> 1;
        if (cCol >= half) { Bm = Bm2; bias = bias2; C = C2; cCol -= half; }
    }

    float acc[MT][NT][4];
    #pragma unroll
    for (int mi = 0; mi < MT; mi++)
        #pragma unroll
        for (int ni = 0; ni < NT; ni++)
            #pragma unroll
            for (int r = 0; r < 4; r++) acc[mi][ni][r] = 0.f;

    constexpr int ACH = 2;
    constexpr int BCH = (TRANSB == 1) ? 2 : (BN == 128 ? 2 : 1);
    float4 pa[ACH], pb[BCH];

    const int ntiles = K / BK;

    #pragma unroll
    for (int c = 0; c < ACH; c++) {
        int flat = c * 256 + tid;
        int r = flat >> 2, qq = flat & 3;
        pa[c] = *(const float4*)(A + (long long)(cRow * BM + r) * lda + qq * 4);
    }
    #pragma unroll
    for (int c = 0; c < BCH; c++) {
        int flat = c * 256 + tid;
        if (TRANSB == 1) {
            int n = flat >> 2, qq = flat & 3;
            pb[c] = *(const float4*)(Bm + (long long)(cCol * BN + n) * ldb + qq * 4);
        } else if (BN == 128) {
            int k = flat >> 5, qq = flat & 31;
            pb[c] = *(const float4*)(Bm + (long long)k * ldb + cCol * BN + qq * 4);
        } else {
            int k = flat >> 4, qq = flat & 15;
            pb[c] = *(const float4*)(Bm + (long long)k * ldb + cCol * BN + qq * 4);
        }
    }

    for (int kt = 0; kt < ntiles; ++kt) {
        #pragma unroll
        for (int c = 0; c < ACH; c++) {
            int flat = c * 256 + tid;
            int r = flat >> 2, qq = flat & 3;
            As[qq * 4 + 0][r] = pa[c].x;
            As[qq * 4 + 1][r] = pa[c].y;
            As[qq * 4 + 2][r] = pa[c].z;
            As[qq * 4 + 3][r] = pa[c].w;
        }
        #pragma unroll
        for (int c = 0; c < BCH; c++) {
            int flat = c * 256 + tid;
            if (TRANSB == 1) {
                int n = flat >> 2, qq = flat & 3;
                Bs[qq * 4 + 0][n] = pb[c].x;
                Bs[qq * 4 + 1][n] = pb[c].y;
                Bs[qq * 4 + 2][n] = pb[c].z;
                Bs[qq * 4 + 3][n] = pb[c].w;
            } else if (BN == 128) {
                int k = flat >> 5, qq = flat & 31;
                *(float4*)&Bs[k][qq * 4] = pb[c];
            } else {
                int k = flat >> 4, qq = flat & 15;
                *(float4*)&Bs[k][qq * 4] = pb[c];
            }
        }
        __syncthreads();

        if (kt + 1 < ntiles) {
            const int k0 = (kt + 1) * BK;
            #pragma unroll
            for (int c = 0; c < ACH; c++) {
                int flat = c * 256 + tid;
                int r = flat >> 2, qq = flat & 3;
                pa[c] = *(const float4*)(A + (long long)(cRow * BM + r) * lda + k0 + qq * 4);
            }
            #pragma unroll
            for (int c = 0; c < BCH; c++) {
                int flat = c * 256 + tid;
                if (TRANSB == 1) {
                    int n = flat >> 2, qq = flat & 3;
                    pb[c] = *(const float4*)(Bm + (long long)(cCol * BN + n) * ldb + k0 + qq * 4);
                } else if (BN == 128) {
                    int k = flat >> 5, qq = flat & 31;
                    pb[c] = *(const float4*)(Bm + (long long)(k0 + k) * ldb + cCol * BN + qq * 4);
                } else {
                    int k = flat >> 4, qq = flat & 15;
                    pb[c] = *(const float4*)(Bm + (long long)(k0 + k) * ldb + cCol * BN + qq * 4);
                }
            }
        }

        #pragma unroll
        for (int kk = 0; kk < BK; kk += 8) {
            uint32_t af[MT][4], bf[NT][2];
            #pragma unroll
            for (int mi = 0; mi < MT; mi++) {
                const int mm0 = wrow * WM + mi * 16;
                af[mi][0] = f2tf32(As[kk + tg    ][mm0 + g]);
                af[mi][1] = f2tf32(As[kk + tg    ][mm0 + g + 8]);
                af[mi][2] = f2tf32(As[kk + tg + 4][mm0 + g]);
                af[mi][3] = f2tf32(As[kk + tg + 4][mm0 + g + 8]);
            }
            #pragma unroll
            for (int ni = 0; ni < NT; ni++) {
                const int n0 = wcol * WN + ni * 8 + g;
                bf[ni][0] = f2tf32(Bs[kk + tg    ][n0]);
                bf[ni][1] = f2tf32(Bs[kk + tg + 4][n0]);
            }
            #pragma unroll
            for (int mi = 0; mi < MT; mi++)
                #pragma unroll
                for (int ni = 0; ni < NT; ni++)
                    mma_tf32(acc[mi][ni], af[mi], bf[ni]);
        }
        __syncthreads();
    }

    #pragma unroll
    for (int mi = 0; mi < MT; mi++) {
        #pragma unroll
        for (int ni = 0; ni < NT; ni++) {
            const int row0 = cRow * BM + wrow * WM + mi * 16 + g;
            const int col0 = cCol * BN + wcol * WN + ni * 8 + 2 * tg;
            float c0 = acc[mi][ni][0];
            float c1 = acc[mi][ni][1];
            float c2 = acc[mi][ni][2];
            float c3 = acc[mi][ni][3];

            if (EPI == 1) {
                const float b0 = bias[col0], b1 = bias[col0 + 1];
                c0 += b0; c1 += b1; c2 += b0; c3 += b1;
            } else if (EPI == 2) {
                const float b0 = bias[col0], b1 = bias[col0 + 1];
                c0 += b0 + res[(long long)row0 * ldc + col0];
                c1 += b1 + res[(long long)row0 * ldc + col0 + 1];
                c2 += b0 + res[(long long)(row0 + 8) * ldc + col0];
                c3 += b1 + res[(long long)(row0 + 8) * ldc + col0 + 1];
            } else if (EPI == 3) {
                const float b0 = bias[col0], b1 = bias[col0 + 1];
                c0 += b0; c1 += b1; c2 += b0; c3 += b1;
                c0 = 0.5f * c0 * (1.0f + erff(c0 * 0.70710678118654752f));
                c1 = 0.5f * c1 * (1.0f + erff(c1 * 0.70710678118654752f));
                c2 = 0.5f * c2 * (1.0f + erff(c2 * 0.70710678118654752f));
                c3 = 0.5f * c3 * (1.0f + erff(c3 * 0.70710678118654752f));
            }

            *(float2*)&C[(long long)row0 * ldc + col0]       = make_float2(c0, c1);
            *(float2*)&C[(long long)(row0 + 8) * ldc + col0] = make_float2(c2, c3);
        }
    }
}

// ---------------------------------------------------------------------------
// Flash attention v2: one CTA = (head-instance z, 128-query tile), 512 threads.
// 16 warps: warp = (key-half h = warp>>3, row-group r = warp&7).
// Each warp: 16 query rows x 64 keys. Double-buffered K/V via cp.async;
// P stays in registers (C-frag -> A-frag via quad shuffles); cross-half
// softmax state combined through a tiny smem exchange each tile.
// ---------------------------------------------------------------------------
constexpr int LDQ = 68, LDK = 68, LDV = 72;
constexpr int SMF_Q   = 0;
constexpr int SMF_K0  = 128 * LDQ;             // 8704
constexpr int SMF_K1  = SMF_K0 + 128 * LDK;    // 17408
constexpr int SMF_V0  = SMF_K1 + 128 * LDK;    // 26112
constexpr int SMF_V1  = SMF_V0 + 128 * LDV;    // 35328
constexpr int SMF_MX  = SMF_V1 + 128 * LDV;    // 44544
constexpr int SMF_SUM = SMF_MX + 256;          // 44800
constexpr int FA_SMEM_BYTES = (SMF_SUM + 256) * 4;  // 180224

__global__ __launch_bounds__(512, 1)
void flash_kernel(const float* __restrict__ Qg, const float* __restrict__ Kg,
                  const float* __restrict__ Vg, const float* __restrict__ maskg,
                  float* __restrict__ Og)
{
    extern __shared__ float sm[];
    uint32_t* Qsu  = (uint32_t*)(sm + SMF_Q);
    float*    smx  = sm + SMF_MX;    // [128][2] running-tile max exchange
    float*    ssum = sm + SMF_SUM;   // [128][2] partial-sum exchange

    const int tid  = threadIdx.x;
    const int warp = tid >> 5;
    const int lane = tid & 31;
    const int g    = lane >> 2;
    const int tg   = lane & 3;
    const int r    = warp & 7;     // row group (16 rows)
    const int h    = warp >> 3;    // key half (64 keys)
    const int m0   = r * 16;
    const int qt   = blockIdx.x;   // 0..15
    const int z    = blockIdx.y;   // 0..63
    const int bi   = z >> 5, kvh = (z >> 2) & 7, qpk = z & 3;

    const float* Qh = Qg + (size_t)bi * Sc * Hc + (size_t)(qt * 128) * Hc
                    + kvh * (QPKc * Dc) + qpk * Dc;
    const float* Kh = Kg + (size_t)bi * Sc * KVc + kvh * Dc;
    const float* Vh = Vg + (size_t)bi * Sc * KVc + kvh * Dc;
    float*       Oh = Og + (size_t)bi * Sc * Hc + (size_t)(qt * 128) * Hc
                    + (kvh * QPKc + qpk) * Dc;
    const float* maskp = maskg + (size_t)bi * Sc;

    // ---- load Q tile (tf32 converted once); 2048 float4 over 512 threads ----
    #pragma unroll
    for (int c = 0; c < 4; c++) {
        int flat = c * 512 + tid, row = flat >> 4, c4 = (flat & 15) * 4;
        float4 qv = *(const float4*)(Qh + (size_t)row * Hc + c4);
        uint32_t* d = Qsu + row * LDQ + c4;
        d[0] = f2tf32(qv.x); d[1] = f2tf32(qv.y);
        d[2] = f2tf32(qv.z); d[3] = f2tf32(qv.w);
    }

    const uint32_t k0_b = (uint32_t)__cvta_generic_to_shared(sm + SMF_K0);
    const uint32_t k1_b = (uint32_t)__cvta_generic_to_shared(sm + SMF_K1);
    const uint32_t v0_b = (uint32_t)__cvta_generic_to_shared(sm + SMF_V0);
    const uint32_t v1_b = (uint32_t)__cvta_generic_to_shared(sm + SMF_V1);

    // ---- prologue: K0,V0 into buffer 0 ----
    {
        #pragma unroll
        for (int c = 0; c < 4; c++) {
            int flat = c * 512 + tid, key = flat >> 4, c4 = (flat & 15) * 4;
            cp_async16(k0_b + (key * LDK + c4) * 4, Kh + (size_t)key * KVc + c4);
        }
        CP_COMMIT();
        #pragma unroll
        for (int c = 0; c < 4; c++) {
            int flat = c * 512 + tid, key = flat >> 4, c4 = (flat & 15) * 4;
            cp_async16(v0_b + (key * LDV + c4) * 4, Vh + (size_t)key * KVc + c4);
        }
        CP_COMMIT();
    }

    float oacc[8][4];
    #pragma unroll
    for (int ni = 0; ni < 8; ni++)
        #pragma unroll
        for (int rr = 0; rr < 4; rr++) oacc[ni][rr] = 0.f;
    float m_lo = -1e30f, m_hi = -1e30f, l_lo = 0.f, l_hi = 0.f;

    for (int t = 0; t < 16; t++) {
        // ---- issue loads for tile t+1 into buffer (t+1)&1 (freed by the
        //      __syncthreads at the end of iteration t-1)
        if (t + 1 < 16) {
            const uint32_t kb = ((t + 1) & 1) ? k1_b : k0_b;
            const uint32_t vb = ((t + 1) & 1) ? v1_b : v0_b;
            const float* Kn = Kh + (size_t)(t + 1) * 128 * KVc;
            const float* Vn = Vh + (size_t)(t + 1) * 128 * KVc;
            #pragma unroll
            for (int c = 0; c < 4; c++) {
                int flat = c * 512 + tid, key = flat >> 4, c4 = (flat & 15) * 4;
                cp_async16(kb + (key * LDK + c4) * 4, Kn + (size_t)key * KVc + c4);
            }
            CP_COMMIT();
            #pragma unroll
            for (int c = 0; c < 4; c++) {
                int flat = c * 512 + tid, key = flat >> 4, c4 = (flat & 15) * 4;
                cp_async16(vb + (key * LDV + c4) * 4, Vn + (size_t)key * KVc + c4);
            }
            CP_COMMIT();
            CP_WAIT(2);              // tile t arrived (t+1 still in flight)
        } else {
            CP_WAIT(0);
        }
        __syncthreads();

        const float* Ks = sm + ((t & 1) ? SMF_K1 : SMF_K0);
        const float* Vs = sm + ((t & 1) ? SMF_V1 : SMF_V0);

        // ================= QK^T: 16 rows x 64 keys (this half) ==============
        float sacc[8][4];
        #pragma unroll
        for (int ni = 0; ni < 8; ni++)
            #pragma unroll
            for (int rr = 0; rr < 4; rr++) sacc[ni][rr] = 0.f;

        #pragma unroll
        for (int kk = 0; kk < 8; kk++) {
            uint32_t af[4];
            af[0] = Qsu[(m0 + g)     * LDQ + kk * 8 + tg];
            af[1] = Qsu[(m0 + g + 8) * LDQ + kk * 8 + tg];
            af[2] = Qsu[(m0 + g)     * LDQ + kk * 8 + tg + 4];
            af[3] = Qsu[(m0 + g + 8) * LDQ + kk * 8 + tg + 4];
            #pragma unroll
            for (int ni = 0; ni < 8; ni++) {
                const int key0 = h * 64 + ni * 8 + g;
                uint32_t bf[2];
                bf[0] = __float_as_uint(Ks[key0 * LDK + kk * 8 + tg]);
                bf[1] = __float_as_uint(Ks[key0 * LDK + kk * 8 + tg + 4]);
                mma_tf32(sacc[ni], af, bf);
            }
        }

        // ================= softmax (cross-half via smem exchange) ===========
        const int k0t = t * 128 + h * 64;
        float mloc_lo = -1e30f, mloc_hi = -1e30f;
        #pragma unroll
        for (int ni = 0; ni < 8; ni++) {
            float2 mk = *(const float2*)(maskp + k0t + ni * 8 + 2 * tg);
            float s0 = fmaf(sacc[ni][0], 0.125f, mk.x);
            float s1 = fmaf(sacc[ni][1], 0.125f, mk.y);
            float s2 = fmaf(sacc[ni][2], 0.125f, mk.x);
            float s3 = fmaf(sacc[ni][3], 0.125f, mk.y);
            sacc[ni][0] = s0; sacc[ni][1] = s1; sacc[ni][2] = s2; sacc[ni][3] = s3;
            mloc_lo = fmaxf(mloc_lo, fmaxf(s0, s1));
            mloc_hi = fmaxf(mloc_hi, fmaxf(s2, s3));
        }
        mloc_lo = fmaxf(mloc_lo, __shfl_xor_sync(0xffffffffu, mloc_lo, 1));
        mloc_lo = fmaxf(mloc_lo, __shfl_xor_sync(0xffffffffu, mloc_lo, 2));
        mloc_hi = fmaxf(mloc_hi, __shfl_xor_sync(0xffffffffu, mloc_hi, 1));
        mloc_hi = fmaxf(mloc_hi, __shfl_xor_sync(0xffffffffu, mloc_hi, 2));

        if (tg == 0) {
            smx[(m0 + g) * 2 + h]     = mloc_lo;
            smx[(m0 + 8 + g) * 2 + h] = mloc_hi;
        }
        __syncthreads();
        const float mo_lo = smx[(m0 + g) * 2 + (1 - h)];
        const float mo_hi = smx[(m0 + 8 + g) * 2 + (1 - h)];

        const float mnew_lo = fmaxf(m_lo, fmaxf(mloc_lo, mo_lo));
        const float mnew_hi = fmaxf(m_hi, fmaxf(mloc_hi, mo_hi));
        const float alpha_lo = fast_exp(m_lo - mnew_lo);
        const float alpha_hi = fast_exp(m_hi - mnew_hi);
        m_lo = mnew_lo; m_hi = mnew_hi;

        float rs_lo = 0.f, rs_hi = 0.f;
        #pragma unroll
        for (int ni = 0; ni < 8; ni++) {
            float p0 = fast_exp(sacc[ni][0] - mnew_lo);
            float p1 = fast_exp(sacc[ni][1] - mnew_lo);
            float p2 = fast_exp(sacc[ni][2] - mnew_hi);
            float p3 = fast_exp(sacc[ni][3] - mnew_hi);
            sacc[ni][0] = p0; sacc[ni][1] = p1; sacc[ni][2] = p2; sacc[ni][3] = p3;
            rs_lo += p0 + p1; rs_hi += p2 + p3;
        }
        rs_lo += __shfl_xor_sync(0xffffffffu, rs_lo, 1);
        rs_lo += __shfl_xor_sync(0xffffffffu, rs_lo, 2);
        rs_hi += __shfl_xor_sync(0xffffffffu, rs_hi, 1);
        rs_hi += __shfl_xor_sync(0xffffffffu, rs_hi, 2);

        if (tg == 0) {
            ssum[(m0 + g) * 2 + h]     = rs_lo;
            ssum[(m0 + 8 + g) * 2 + h] = rs_hi;
        }
        __syncthreads();
        l_lo = fmaf(l_lo, alpha_lo, rs_lo + ssum[(m0 + g) * 2 + (1 - h)]);
        l_hi = fmaf(l_hi, alpha_hi, rs_hi + ssum[(m0 + 8 + g) * 2 + (1 - h)]);

        #pragma unroll
        for (int ni = 0; ni < 8; ni++) {
            oacc[ni][0] *= alpha_lo; oacc[ni][1] *= alpha_lo;
            oacc[ni][2] *= alpha_hi; oacc[ni][3] *= alpha_hi;
        }

        // ================= PV: O += P(16x64) @ V(64x64) =====================
        // A-fragment built from C-fragment layout via intra-quad shuffles:
        // C holds cols {2tg, 2tg+1}; A needs {tg, tg+4}.
        const int srcA = (lane & ~3) | (tg >> 1);
        const int selb = tg & 1;
        #pragma unroll
        for (int kk = 0; kk < 8; kk++) {
            float c0 = sacc[kk][0], c1 = sacc[kk][1];
            float c2 = sacc[kk][2], c3 = sacc[kk][3];
            float s0  = __shfl_sync(0xffffffffu, c0, srcA);
            float s1  = __shfl_sync(0xffffffffu, c1, srcA);
            float s0b = __shfl_sync(0xffffffffu, c0, srcA + 2);
            float s1b = __shfl_sync(0xffffffffu, c1, srcA + 2);
            float s2  = __shfl_sync(0xffffffffu, c2, srcA);
            float s3  = __shfl_sync(0xffffffffu, c3, srcA);
            float s2b = __shfl_sync(0xffffffffu, c2, srcA + 2);
            float s3b = __shfl_sync(0xffffffffu, c3, srcA + 2);
            uint32_t af[4];
            af[0] = __float_as_uint(selb ? s1  : s0);
            af[1] = __float_as_uint(selb ? s3  : s2);
            af[2] = __float_as_uint(selb ? s1b : s0b);
            af[3] = __float_as_uint(selb ? s3b : s2b);
            const int vr0 = h * 64 + kk * 8 + tg;
            #pragma unroll
            for (int ni = 0; ni < 8; ni++) {
                uint32_t bf[2];
                bf[0] = __float_as_uint(Vs[vr0       * LDV + ni * 8 + g]);
                bf[1] = __float_as_uint(Vs[(vr0 + 4) * LDV + ni * 8 + g]);
                mma_tf32(oacc[ni], af, bf);
            }
        }
        __syncthreads();   // all warps done with buffer t -> free for t+2 issue
    }

    // ---- combine halves + finalize (reuse V0 region as [128][72] scratch) ----
    float* smo = sm + SMF_V0;
    if (h == 1) {
        #pragma unroll
        for (int ni = 0; ni < 8; ni++) {
            *(float2*)&smo[(m0 + g)     * LDV + ni * 8 + 2 * tg] =
                make_float2(oacc[ni][0], oacc[ni][1]);
            *(float2*)&smo[(m0 + 8 + g) * LDV + ni * 8 + 2 * tg] =
                make_float2(oacc[ni][2], oacc[ni][3]);
        }
    }
    __syncthreads();
    if (h == 0) {
        const float inv_lo = 1.0f / l_lo;
        const float inv_hi = 1.0f / l_hi;
        #pragma unroll
        for (int ni = 0; ni < 8; ni++) {
            const int col = ni * 8 + 2 * tg;
            float2 a = *(float2*)&smo[(m0 + g)     * LDV + col];
            float2 b = *(float2*)&smo[(m0 + 8 + g) * LDV + col];
            *(float2*)(Oh + (size_t)(m0 + g)     * Hc + col) =
                make_float2((oacc[ni][0] + a.x) * inv_lo, (oacc[ni][1] + a.y) * inv_lo);
            *(float2*)(Oh + (size_t)(m0 + 8 + g) * Hc + col) =
                make_float2((oacc[ni][2] + b.x) * inv_hi, (oacc[ni][3] + b.y) * inv_hi);
        }
    }
}

// ---------------------------------------------------------------------------
// Launch sequence
// ---------------------------------------------------------------------------
extern "C" void kernel_launch(void* const* d_in, const int* in_sizes, int n_in,
                              void* d_out, int out_size)
{
    const float* x    = (const float*)d_in[0];
    const float* mask = (const float*)d_in[1];
    const float* Wq   = (const float*)d_in[2];
    const float* bq   = (const float*)d_in[3];
    const float* Wk   = (const float*)d_in[4];
    const float* bk   = (const float*)d_in[5];
    const float* Wv   = (const float*)d_in[6];
    const float* bv   = (const float*)d_in[7];
    const float* Wo   = (const float*)d_in[8];
    const float* bo   = (const float*)d_in[9];
    const float* W1   = (const float*)d_in[10];
    const float* b1   = (const float*)d_in[11];
    const float* W2   = (const float*)d_in[12];
    const float* b2   = (const float*)d_in[13];
    const float* g1   = (const float*)d_in[14];
    const float* be1  = (const float*)d_in[15];
    const float* g2   = (const float*)d_in[16];
    const float* be2  = (const float*)d_in[17];
    float* out = (float*)d_out;

    float *h, *q, *kq, *vq, *o, *x1, *h2, *m1;
    cudaGetSymbolAddress((void**)&h,  g_h);
    cudaGetSymbolAddress((void**)&q,  g_q);
    cudaGetSymbolAddress((void**)&kq, g_k);
    cudaGetSymbolAddress((void**)&vq, g_v);
    cudaGetSymbolAddress((void**)&o,  g_o);
    cudaGetSymbolAddress((void**)&x1, g_x1);
    cudaGetSymbolAddress((void**)&h2, g_h2);
    cudaGetSymbolAddress((void**)&m1, g_m1);

    // Not a stream op; deterministic and capture-safe to call every time.
    cudaFuncSetAttribute(flash_kernel,
                         cudaFuncAttributeMaxDynamicSharedMemorySize,
                         FA_SMEM_BYTES);

    // 1) h = LN(x)
    ln_kernel<<<MR, 256>>>(x, g1, be1, h);

    // 2) Q projection
    gemm_tc<128, 0, 1, 0><<<dim3(Hc / 128, MR / 128), 256>>>(
        h, Hc, Wq, Hc, q, Hc, MR, Hc, Hc, bq, nullptr, nullptr, nullptr, nullptr);

    // 3) K + V projections fused into one launch (256 CTAs)
    gemm_tc<128, 0, 1, 1><<<dim3(2 * KVc / 128, MR / 128), 256>>>(
        h, Hc, Wk, KVc, kq, KVc, MR, KVc, Hc, bk, nullptr, Wv, bv, vq);

    // 4) fused flash attention -> o
    flash_kernel<<<dim3(16, NHEADZ), 512, FA_SMEM_BYTES>>>(q, kq, vq, mask, o);

    // 5) x1 = x + o @ Wo + bo
    gemm_tc<128, 0, 2, 0><<<dim3(Hc / 128, MR / 128), 256>>>(
        o, Hc, Wo, Hc, x1, Hc, MR, Hc, Hc, bo, x, nullptr, nullptr, nullptr);

    // 6) h2 = LN(x1)
    ln_kernel<<<MR, 256>>>(x1, g2, be2, h2);

    // 7) m1 = gelu(h2 @ W1 + b1)
    gemm_tc<128, 0, 3, 0><<<dim3(FFc / 128, MR / 128), 256>>>(
        h2, Hc, W1, FFc, m1, FFc, MR, FFc, Hc, b1, nullptr, nullptr, nullptr, nullptr);

    // 8) out = x1 + m1 @ W2 + b2
    gemm_tc<128, 0, 2, 0><<<dim3(Hc / 128, MR / 128), 256>>>(
        m1, FFc, W2, Hc, out, Hc, MR, Hc, FFc, b2, x1, nullptr, nullptr, nullptr);
}

// round 8
// speedup vs baseline: 3.7521x; 1.1790x over previous
#include <cuda_runtime.h>
#include <math.h>
#include <stdint.h>

// ---------------------------------------------------------------------------
// Problem constants (fixed shapes)
// ---------------------------------------------------------------------------
constexpr int Bc   = 2;
constexpr int Sc   = 2048;
constexpr int Hc   = 2048;
constexpr int KVHc = 8;
constexpr int QPKc = 4;
constexpr int Dc   = 64;
constexpr int KVc  = 512;    // KVH * D
constexpr int FFc  = 8192;
constexpr int MR   = Bc * Sc;            // 4096 rows
constexpr int NHEADZ = Bc * KVHc * QPKc; // 64 head instances

// ---------------------------------------------------------------------------
// Scratch (device globals; no runtime allocation allowed)
// ---------------------------------------------------------------------------
__device__ float g_h  [(size_t)MR * Hc];
__device__ float g_q  [(size_t)MR * Hc];
__device__ float g_k  [(size_t)MR * KVc];
__device__ float g_v  [(size_t)MR * KVc];
__device__ float g_o  [(size_t)MR * Hc];
__device__ float g_x1 [(size_t)MR * Hc];
__device__ float g_h2 [(size_t)MR * Hc];
__device__ float g_m1 [(size_t)MR * FFc];

// ---------------------------------------------------------------------------
// Helpers
// ---------------------------------------------------------------------------
__device__ __forceinline__ uint32_t f2tf32(float f) {
    uint32_t u;
    asm("cvt.rna.tf32.f32 %0, %1;" : "=r"(u) : "f"(f));
    return u;
}

__device__ __forceinline__ void mma_tf32(float* c, const uint32_t* a, const uint32_t* b) {
    asm volatile(
        "mma.sync.aligned.m16n8k8.row.col.f32.tf32.tf32.f32 "
        "{%0,%1,%2,%3}, {%4,%5,%6,%7}, {%8,%9}, {%0,%1,%2,%3};\n"
        : "+f"(c[0]), "+f"(c[1]), "+f"(c[2]), "+f"(c[3])
        : "r"(a[0]), "r"(a[1]), "r"(a[2]), "r"(a[3]),
          "r"(b[0]), "r"(b[1]));
}

// FFMA-only exp; x <= 0 expected. rel err ~3e-6.
__device__ __forceinline__ float fast_exp(float x) {
    float y = x * 1.4426950408889634f;
    y = fmaxf(y, -126.0f);
    float z = y + 12582912.0f;
    int   n = __float_as_int(z) - 0x4B400000;
    float f = y - (z - 12582912.0f);
    float p =             1.3333558146428443e-3f;
    p = fmaf(p, f,        9.6181291076284772e-3f);
    p = fmaf(p, f,        5.5504108664821580e-2f);
    p = fmaf(p, f,        2.4022650695910072e-1f);
    p = fmaf(p, f,        6.9314718055994531e-1f);
    p = fmaf(p, f,        1.0f);
    return p * __int_as_float((n + 127) << 23);
}

__device__ __forceinline__ void cp_async16(uint32_t dst, const void* src) {
    asm volatile("cp.async.cg.shared.global [%0], [%1], 16;" :: "r"(dst), "l"(src));
}
#define CP_COMMIT()  asm volatile("cp.async.commit_group;\n" ::: "memory")
#define CP_WAIT(N)   asm volatile("cp.async.wait_group %0;\n" :: "n"(N) : "memory")

// ---------------------------------------------------------------------------
// LayerNorm
// ---------------------------------------------------------------------------
__global__ void ln_kernel(const float* __restrict__ x,
                          const float* __restrict__ g,
                          const float* __restrict__ b,
                          float* __restrict__ out)
{
    const int HD = Hc;
    const long long row = blockIdx.x;
    const float* xr = x + row * HD;
    float* outr = out + row * HD;
    const int tid = threadIdx.x;

    float4 v0 = *(const float4*)(xr + tid * 8);
    float4 v1 = *(const float4*)(xr + tid * 8 + 4);
    float s  = v0.x + v0.y + v0.z + v0.w + v1.x + v1.y + v1.z + v1.w;
    float sq = v0.x*v0.x + v0.y*v0.y + v0.z*v0.z + v0.w*v0.w
             + v1.x*v1.x + v1.y*v1.y + v1.z*v1.z + v1.w*v1.w;

    #pragma unroll
    for (int o = 16; o; o >>= 1) {
        s  += __shfl_xor_sync(0xffffffffu, s,  o);
        sq += __shfl_xor_sync(0xffffffffu, sq, o);
    }
    __shared__ float ss[8], ssq[8];
    if ((tid & 31) == 0) { ss[tid >> 5] = s; ssq[tid >> 5] = sq; }
    __syncthreads();
    float ts = 0.f, tsq = 0.f;
    #pragma unroll
    for (int i = 0; i < 8; i++) { ts += ss[i]; tsq += ssq[i]; }

    const float mu  = ts * (1.0f / HD);
    const float var = tsq * (1.0f / HD) - mu * mu;
    const float inv = rsqrtf(var + 1e-5f);

    float4 gg0 = *(const float4*)(g + tid * 8);
    float4 gg1 = *(const float4*)(g + tid * 8 + 4);
    float4 bb0 = *(const float4*)(b + tid * 8);
    float4 bb1 = *(const float4*)(b + tid * 8 + 4);

    float4 o0, o1;
    o0.x = (v0.x - mu) * inv * gg0.x + bb0.x;
    o0.y = (v0.y - mu) * inv * gg0.y + bb0.y;
    o0.z = (v0.z - mu) * inv * gg0.z + bb0.z;
    o0.w = (v0.w - mu) * inv * gg0.w + bb0.w;
    o1.x = (v1.x - mu) * inv * gg1.x + bb1.x;
    o1.y = (v1.y - mu) * inv * gg1.y + bb1.y;
    o1.z = (v1.z - mu) * inv * gg1.z + bb1.z;
    o1.w = (v1.w - mu) * inv * gg1.w + bb1.w;
    *(float4*)(outr + tid * 8)     = o0;
    *(float4*)(outr + tid * 8 + 4) = o1;
}

// ---------------------------------------------------------------------------
// tf32 GEMM v4: 128x128x16 tiles, STATIC 2-stage cp.async double buffer
// (same commit/wait/sync pattern as the verified flash kernel), raw
// fp32-as-tf32 operands (no cvt in hot loop), 2 CTAs/SM.
//   A: [M,K] row-major; B: [K,N] row-major.
//   Stage: As[128][20] (rows 80B, 16B-aligned; fragment banks (20g+tg)%32
//   conflict-free) + Bs[16][136]. 2 stages = 37888 B static smem (< 48KB,
//   no cudaFuncSetAttribute needed).
//   EPI: 1 +bias, 2 res+acc+bias, 3 gelu(acc+bias)
//   KVSEL=1: grid.x doubled; second half uses Bm2/bias2/C2 (fused K+V proj).
// ---------------------------------------------------------------------------
constexpr int G_LDA   = 20;
constexpr int G_LDB   = 136;
constexpr int G_ASZ   = 128 * G_LDA;            // 2560 floats
constexpr int G_STAGE = G_ASZ + 16 * G_LDB;     // 4736 floats (18944 B)

template<int EPI, int KVSEL>
__global__ __launch_bounds__(256, 2)
void gemm4(const float* __restrict__ A, int lda,
           const float* __restrict__ Bm, int ldb,
           float* __restrict__ C, int ldc,
           int K,
           const float* __restrict__ bias,
           const float* __restrict__ res,
           const float* __restrict__ Bm2,
           const float* __restrict__ bias2,
           float* __restrict__ C2)
{
    __shared__ float smem[2 * G_STAGE];

    const int tid  = threadIdx.x;
    const int warp = tid >> 5;
    const int lane = tid & 31;
    const int g    = lane >> 2;
    const int tg   = lane & 3;
    const int wrow = warp >> 2;   // 0..1
    const int wcol = warp & 3;    // 0..3

    const int cRow = blockIdx.y;
    int cCol = blockIdx.x;
    if (KVSEL) {
        const int half = gridDim.x >> 1;
        if (cCol >= half) { Bm = Bm2; bias = bias2; C = C2; cCol -= half; }
    }

    const uint32_t smem_b = (uint32_t)__cvta_generic_to_shared(smem);
    const float* Ab = A + (size_t)(cRow * 128) * lda;
    const float* Bb = Bm + cCol * 128;

    float acc[4][4][4];
    #pragma unroll
    for (int mi = 0; mi < 4; mi++)
        #pragma unroll
        for (int ni = 0; ni < 4; ni++)
            #pragma unroll
            for (int r = 0; r < 4; r++) acc[mi][ni][r] = 0.f;

    const int ntiles = K >> 4;

    // cp.async coords for this thread
    const int arow0 = tid >> 2, acol0 = (tid & 3) * 4;
    const int bk0   = tid >> 5, bn0   = (tid & 31) * 4;

    // ---- prologue: tile 0 into stage 0 ----
    {
        const uint32_t st = smem_b;
        #pragma unroll
        for (int c = 0; c < 2; c++) {
            int row = arow0 + c * 64;
            cp_async16(st + (row * G_LDA + acol0) * 4,
                       Ab + (size_t)row * lda + acol0);
        }
        #pragma unroll
        for (int c = 0; c < 2; c++) {
            int k = bk0 + c * 8;
            cp_async16(st + (G_ASZ + k * G_LDB + bn0) * 4,
                       Bb + (size_t)k * ldb + bn0);
        }
        CP_COMMIT();
    }

    for (int kt = 0; kt < ntiles; ++kt) {
        // ---- issue tile kt+1 into the other stage (freed by end-of-iter
        //      sync of iteration kt-1), then wait for tile kt ----
        if (kt + 1 < ntiles) {
            const int k0 = (kt + 1) * 16;
            const uint32_t st = smem_b + ((kt + 1) & 1) * G_STAGE * 4;
            #pragma unroll
            for (int c = 0; c < 2; c++) {
                int row = arow0 + c * 64;
                cp_async16(st + (row * G_LDA + acol0) * 4,
                           Ab + (size_t)row * lda + k0 + acol0);
            }
            #pragma unroll
            for (int c = 0; c < 2; c++) {
                int k = bk0 + c * 8;
                cp_async16(st + (G_ASZ + k * G_LDB + bn0) * 4,
                           Bb + (size_t)(k0 + k) * ldb + bn0);
            }
            CP_COMMIT();
            CP_WAIT(1);
        } else {
            CP_WAIT(0);
        }
        __syncthreads();

        const float* As = smem + (kt & 1) * G_STAGE;
        const float* Bs = As + G_ASZ;

        #pragma unroll
        for (int kk = 0; kk < 16; kk += 8) {
            uint32_t af[4][4], bf[4][2];
            #pragma unroll
            for (int mi = 0; mi < 4; mi++) {
                const int mm0 = wrow * 64 + mi * 16;
                af[mi][0] = __float_as_uint(As[(mm0 + g)     * G_LDA + kk + tg]);
                af[mi][1] = __float_as_uint(As[(mm0 + g + 8) * G_LDA + kk + tg]);
                af[mi][2] = __float_as_uint(As[(mm0 + g)     * G_LDA + kk + tg + 4]);
                af[mi][3] = __float_as_uint(As[(mm0 + g + 8) * G_LDA + kk + tg + 4]);
            }
            #pragma unroll
            for (int ni = 0; ni < 4; ni++) {
                const int n0 = wcol * 32 + ni * 8 + g;
                bf[ni][0] = __float_as_uint(Bs[(kk + tg)     * G_LDB + n0]);
                bf[ni][1] = __float_as_uint(Bs[(kk + tg + 4) * G_LDB + n0]);
            }
            #pragma unroll
            for (int mi = 0; mi < 4; mi++)
                #pragma unroll
                for (int ni = 0; ni < 4; ni++)
                    mma_tf32(acc[mi][ni], af[mi], bf[ni]);
        }
        __syncthreads();   // free stage kt&1 for iteration kt+1's issue
    }

    // ---- epilogue ----
    #pragma unroll
    for (int mi = 0; mi < 4; mi++) {
        #pragma unroll
        for (int ni = 0; ni < 4; ni++) {
            const int row0 = cRow * 128 + wrow * 64 + mi * 16 + g;
            const int col0 = cCol * 128 + wcol * 32 + ni * 8 + 2 * tg;
            float c0 = acc[mi][ni][0];
            float c1 = acc[mi][ni][1];
            float c2 = acc[mi][ni][2];
            float c3 = acc[mi][ni][3];

            if (EPI == 1) {
                const float b0 = bias[col0], b1 = bias[col0 + 1];
                c0 += b0; c1 += b1; c2 += b0; c3 += b1;
            } else if (EPI == 2) {
                const float b0 = bias[col0], b1 = bias[col0 + 1];
                c0 += b0 + res[(size_t)row0 * ldc + col0];
                c1 += b1 + res[(size_t)row0 * ldc + col0 + 1];
                c2 += b0 + res[(size_t)(row0 + 8) * ldc + col0];
                c3 += b1 + res[(size_t)(row0 + 8) * ldc + col0 + 1];
            } else if (EPI == 3) {
                const float b0 = bias[col0], b1 = bias[col0 + 1];
                c0 += b0; c1 += b1; c2 += b0; c3 += b1;
                c0 = 0.5f * c0 * (1.0f + erff(c0 * 0.70710678118654752f));
                c1 = 0.5f * c1 * (1.0f + erff(c1 * 0.70710678118654752f));
                c2 = 0.5f * c2 * (1.0f + erff(c2 * 0.70710678118654752f));
                c3 = 0.5f * c3 * (1.0f + erff(c3 * 0.70710678118654752f));
            }

            *(float2*)&C[(size_t)row0 * ldc + col0]       = make_float2(c0, c1);
            *(float2*)&C[(size_t)(row0 + 8) * ldc + col0] = make_float2(c2, c3);
        }
    }
}

// ---------------------------------------------------------------------------
// Flash attention v2 (unchanged from round 5 — 692us, verified).
// ---------------------------------------------------------------------------
constexpr int LDQ = 68, LDK = 68, LDV = 72;
constexpr int SMF_Q   = 0;
constexpr int SMF_K0  = 128 * LDQ;
constexpr int SMF_K1  = SMF_K0 + 128 * LDK;
constexpr int SMF_V0  = SMF_K1 + 128 * LDK;
constexpr int SMF_V1  = SMF_V0 + 128 * LDV;
constexpr int SMF_MX  = SMF_V1 + 128 * LDV;
constexpr int SMF_SUM = SMF_MX + 256;
constexpr int FA_SMEM_BYTES = (SMF_SUM + 256) * 4;  // 180224

__global__ __launch_bounds__(512, 1)
void flash_kernel(const float* __restrict__ Qg, const float* __restrict__ Kg,
                  const float* __restrict__ Vg, const float* __restrict__ maskg,
                  float* __restrict__ Og)
{
    extern __shared__ float sm[];
    uint32_t* Qsu  = (uint32_t*)(sm + SMF_Q);
    float*    smx  = sm + SMF_MX;
    float*    ssum = sm + SMF_SUM;

    const int tid  = threadIdx.x;
    const int warp = tid >> 5;
    const int lane = tid & 31;
    const int g    = lane >> 2;
    const int tg   = lane & 3;
    const int r    = warp & 7;
    const int h    = warp >> 3;
    const int m0   = r * 16;
    const int qt   = blockIdx.x;
    const int z    = blockIdx.y;
    const int bi   = z >> 5, kvh = (z >> 2) & 7, qpk = z & 3;

    const float* Qh = Qg + (size_t)bi * Sc * Hc + (size_t)(qt * 128) * Hc
                    + kvh * (QPKc * Dc) + qpk * Dc;
    const float* Kh = Kg + (size_t)bi * Sc * KVc + kvh * Dc;
    const float* Vh = Vg + (size_t)bi * Sc * KVc + kvh * Dc;
    float*       Oh = Og + (size_t)bi * Sc * Hc + (size_t)(qt * 128) * Hc
                    + (kvh * QPKc + qpk) * Dc;
    const float* maskp = maskg + (size_t)bi * Sc;

    #pragma unroll
    for (int c = 0; c < 4; c++) {
        int flat = c * 512 + tid, row = flat >> 4, c4 = (flat & 15) * 4;
        float4 qv = *(const float4*)(Qh + (size_t)row * Hc + c4);
        uint32_t* d = Qsu + row * LDQ + c4;
        d[0] = f2tf32(qv.x); d[1] = f2tf32(qv.y);
        d[2] = f2tf32(qv.z); d[3] = f2tf32(qv.w);
    }

    const uint32_t k0_b = (uint32_t)__cvta_generic_to_shared(sm + SMF_K0);
    const uint32_t k1_b = (uint32_t)__cvta_generic_to_shared(sm + SMF_K1);
    const uint32_t v0_b = (uint32_t)__cvta_generic_to_shared(sm + SMF_V0);
    const uint32_t v1_b = (uint32_t)__cvta_generic_to_shared(sm + SMF_V1);

    {
        #pragma unroll
        for (int c = 0; c < 4; c++) {
            int flat = c * 512 + tid, key = flat >> 4, c4 = (flat & 15) * 4;
            cp_async16(k0_b + (key * LDK + c4) * 4, Kh + (size_t)key * KVc + c4);
        }
        CP_COMMIT();
        #pragma unroll
        for (int c = 0; c < 4; c++) {
            int flat = c * 512 + tid, key = flat >> 4, c4 = (flat & 15) * 4;
            cp_async16(v0_b + (key * LDV + c4) * 4, Vh + (size_t)key * KVc + c4);
        }
        CP_COMMIT();
    }

    float oacc[8][4];
    #pragma unroll
    for (int ni = 0; ni < 8; ni++)
        #pragma unroll
        for (int rr = 0; rr < 4; rr++) oacc[ni][rr] = 0.f;
    float m_lo = -1e30f, m_hi = -1e30f, l_lo = 0.f, l_hi = 0.f;

    for (int t = 0; t < 16; t++) {
        if (t + 1 < 16) {
            const uint32_t kb = ((t + 1) & 1) ? k1_b : k0_b;
            const uint32_t vb = ((t + 1) & 1) ? v1_b : v0_b;
            const float* Kn = Kh + (size_t)(t + 1) * 128 * KVc;
            const float* Vn = Vh + (size_t)(t + 1) * 128 * KVc;
            #pragma unroll
            for (int c = 0; c < 4; c++) {
                int flat = c * 512 + tid, key = flat >> 4, c4 = (flat & 15) * 4;
                cp_async16(kb + (key * LDK + c4) * 4, Kn + (size_t)key * KVc + c4);
            }
            CP_COMMIT();
            #pragma unroll
            for (int c = 0; c < 4; c++) {
                int flat = c * 512 + tid, key = flat >> 4, c4 = (flat & 15) * 4;
                cp_async16(vb + (key * LDV + c4) * 4, Vn + (size_t)key * KVc + c4);
            }
            CP_COMMIT();
            CP_WAIT(2);
        } else {
            CP_WAIT(0);
        }
        __syncthreads();

        const float* Ks = sm + ((t & 1) ? SMF_K1 : SMF_K0);
        const float* Vs = sm + ((t & 1) ? SMF_V1 : SMF_V0);

        float sacc[8][4];
        #pragma unroll
        for (int ni = 0; ni < 8; ni++)
            #pragma unroll
            for (int rr = 0; rr < 4; rr++) sacc[ni][rr] = 0.f;

        #pragma unroll
        for (int kk = 0; kk < 8; kk++) {
            uint32_t af[4];
            af[0] = Qsu[(m0 + g)     * LDQ + kk * 8 + tg];
            af[1] = Qsu[(m0 + g + 8) * LDQ + kk * 8 + tg];
            af[2] = Qsu[(m0 + g)     * LDQ + kk * 8 + tg + 4];
            af[3] = Qsu[(m0 + g + 8) * LDQ + kk * 8 + tg + 4];
            #pragma unroll
            for (int ni = 0; ni < 8; ni++) {
                const int key0 = h * 64 + ni * 8 + g;
                uint32_t bf[2];
                bf[0] = __float_as_uint(Ks[key0 * LDK + kk * 8 + tg]);
                bf[1] = __float_as_uint(Ks[key0 * LDK + kk * 8 + tg + 4]);
                mma_tf32(sacc[ni], af, bf);
            }
        }

        const int k0t = t * 128 + h * 64;
        float mloc_lo = -1e30f, mloc_hi = -1e30f;
        #pragma unroll
        for (int ni = 0; ni < 8; ni++) {
            float2 mk = *(const float2*)(maskp + k0t + ni * 8 + 2 * tg);
            float s0 = fmaf(sacc[ni][0], 0.125f, mk.x);
            float s1 = fmaf(sacc[ni][1], 0.125f, mk.y);
            float s2 = fmaf(sacc[ni][2], 0.125f, mk.x);
            float s3 = fmaf(sacc[ni][3], 0.125f, mk.y);
            sacc[ni][0] = s0; sacc[ni][1] = s1; sacc[ni][2] = s2; sacc[ni][3] = s3;
            mloc_lo = fmaxf(mloc_lo, fmaxf(s0, s1));
            mloc_hi = fmaxf(mloc_hi, fmaxf(s2, s3));
        }
        mloc_lo = fmaxf(mloc_lo, __shfl_xor_sync(0xffffffffu, mloc_lo, 1));
        mloc_lo = fmaxf(mloc_lo, __shfl_xor_sync(0xffffffffu, mloc_lo, 2));
        mloc_hi = fmaxf(mloc_hi, __shfl_xor_sync(0xffffffffu, mloc_hi, 1));
        mloc_hi = fmaxf(mloc_hi, __shfl_xor_sync(0xffffffffu, mloc_hi, 2));

        if (tg == 0) {
            smx[(m0 + g) * 2 + h]     = mloc_lo;
            smx[(m0 + 8 + g) * 2 + h] = mloc_hi;
        }
        __syncthreads();
        const float mo_lo = smx[(m0 + g) * 2 + (1 - h)];
        const float mo_hi = smx[(m0 + 8 + g) * 2 + (1 - h)];

        const float mnew_lo = fmaxf(m_lo, fmaxf(mloc_lo, mo_lo));
        const float mnew_hi = fmaxf(m_hi, fmaxf(mloc_hi, mo_hi));
        const float alpha_lo = fast_exp(m_lo - mnew_lo);
        const float alpha_hi = fast_exp(m_hi - mnew_hi);
        m_lo = mnew_lo; m_hi = mnew_hi;

        float rs_lo = 0.f, rs_hi = 0.f;
        #pragma unroll
        for (int ni = 0; ni < 8; ni++) {
            float p0 = fast_exp(sacc[ni][0] - mnew_lo);
            float p1 = fast_exp(sacc[ni][1] - mnew_lo);
            float p2 = fast_exp(sacc[ni][2] - mnew_hi);
            float p3 = fast_exp(sacc[ni][3] - mnew_hi);
            sacc[ni][0] = p0; sacc[ni][1] = p1; sacc[ni][2] = p2; sacc[ni][3] = p3;
            rs_lo += p0 + p1; rs_hi += p2 + p3;
        }
        rs_lo += __shfl_xor_sync(0xffffffffu, rs_lo, 1);
        rs_lo += __shfl_xor_sync(0xffffffffu, rs_lo, 2);
        rs_hi += __shfl_xor_sync(0xffffffffu, rs_hi, 1);
        rs_hi += __shfl_xor_sync(0xffffffffu, rs_hi, 2);

        if (tg == 0) {
            ssum[(m0 + g) * 2 + h]     = rs_lo;
            ssum[(m0 + 8 + g) * 2 + h] = rs_hi;
        }
        __syncthreads();
        l_lo = fmaf(l_lo, alpha_lo, rs_lo + ssum[(m0 + g) * 2 + (1 - h)]);
        l_hi = fmaf(l_hi, alpha_hi, rs_hi + ssum[(m0 + 8 + g) * 2 + (1 - h)]);

        #pragma unroll
        for (int ni = 0; ni < 8; ni++) {
            oacc[ni][0] *= alpha_lo; oacc[ni][1] *= alpha_lo;
            oacc[ni][2] *= alpha_hi; oacc[ni][3] *= alpha_hi;
        }

        const int srcA = (lane & ~3) | (tg >> 1);
        const int selb = tg & 1;
        #pragma unroll
        for (int kk = 0; kk < 8; kk++) {
            float c0 = sacc[kk][0], c1 = sacc[kk][1];
            float c2 = sacc[kk][2], c3 = sacc[kk][3];
            float s0  = __shfl_sync(0xffffffffu, c0, srcA);
            float s1  = __shfl_sync(0xffffffffu, c1, srcA);
            float s0b = __shfl_sync(0xffffffffu, c0, srcA + 2);
            float s1b = __shfl_sync(0xffffffffu, c1, srcA + 2);
            float s2  = __shfl_sync(0xffffffffu, c2, srcA);
            float s3  = __shfl_sync(0xffffffffu, c3, srcA);
            float s2b = __shfl_sync(0xffffffffu, c2, srcA + 2);
            float s3b = __shfl_sync(0xffffffffu, c3, srcA + 2);
            uint32_t af[4];
            af[0] = __float_as_uint(selb ? s1  : s0);
            af[1] = __float_as_uint(selb ? s3  : s2);
            af[2] = __float_as_uint(selb ? s1b : s0b);
            af[3] = __float_as_uint(selb ? s3b : s2b);
            const int vr0 = h * 64 + kk * 8 + tg;
            #pragma unroll
            for (int ni = 0; ni < 8; ni++) {
                uint32_t bf[2];
                bf[0] = __float_as_uint(Vs[vr0       * LDV + ni * 8 + g]);
                bf[1] = __float_as_uint(Vs[(vr0 + 4) * LDV + ni * 8 + g]);
                mma_tf32(oacc[ni], af, bf);
            }
        }
        __syncthreads();
    }

    float* smo = sm + SMF_V0;
    if (h == 1) {
        #pragma unroll
        for (int ni = 0; ni < 8; ni++) {
            *(float2*)&smo[(m0 + g)     * LDV + ni * 8 + 2 * tg] =
                make_float2(oacc[ni][0], oacc[ni][1]);
            *(float2*)&smo[(m0 + 8 + g) * LDV + ni * 8 + 2 * tg] =
                make_float2(oacc[ni][2], oacc[ni][3]);
        }
    }
    __syncthreads();
    if (h == 0) {
        const float inv_lo = 1.0f / l_lo;
        const float inv_hi = 1.0f / l_hi;
        #pragma unroll
        for (int ni = 0; ni < 8; ni++) {
            const int col = ni * 8 + 2 * tg;
            float2 a = *(float2*)&smo[(m0 + g)     * LDV + col];
            float2 b = *(float2*)&smo[(m0 + 8 + g) * LDV + col];
            *(float2*)(Oh + (size_t)(m0 + g)     * Hc + col) =
                make_float2((oacc[ni][0] + a.x) * inv_lo, (oacc[ni][1] + a.y) * inv_lo);
            *(float2*)(Oh + (size_t)(m0 + 8 + g) * Hc + col) =
                make_float2((oacc[ni][2] + b.x) * inv_hi, (oacc[ni][3] + b.y) * inv_hi);
        }
    }
}

// ---------------------------------------------------------------------------
// Launch sequence
// ---------------------------------------------------------------------------
extern "C" void kernel_launch(void* const* d_in, const int* in_sizes, int n_in,
                              void* d_out, int out_size)
{
    const float* x    = (const float*)d_in[0];
    const float* mask = (const float*)d_in[1];
    const float* Wq   = (const float*)d_in[2];
    const float* bq   = (const float*)d_in[3];
    const float* Wk   = (const float*)d_in[4];
    const float* bk   = (const float*)d_in[5];
    const float* Wv   = (const float*)d_in[6];
    const float* bv   = (const float*)d_in[7];
    const float* Wo   = (const float*)d_in[8];
    const float* bo   = (const float*)d_in[9];
    const float* W1   = (const float*)d_in[10];
    const float* b1   = (const float*)d_in[11];
    const float* W2   = (const float*)d_in[12];
    const float* b2   = (const float*)d_in[13];
    const float* g1   = (const float*)d_in[14];
    const float* be1  = (const float*)d_in[15];
    const float* g2   = (const float*)d_in[16];
    const float* be2  = (const float*)d_in[17];
    float* out = (float*)d_out;

    float *h, *q, *kq, *vq, *o, *x1, *h2, *m1;
    cudaGetSymbolAddress((void**)&h,  g_h);
    cudaGetSymbolAddress((void**)&q,  g_q);
    cudaGetSymbolAddress((void**)&kq, g_k);
    cudaGetSymbolAddress((void**)&vq, g_v);
    cudaGetSymbolAddress((void**)&o,  g_o);
    cudaGetSymbolAddress((void**)&x1, g_x1);
    cudaGetSymbolAddress((void**)&h2, g_h2);
    cudaGetSymbolAddress((void**)&m1, g_m1);

    // Only flash needs >48KB dynamic smem (this exact call passed in R3/R5).
    cudaFuncSetAttribute(flash_kernel,
                         cudaFuncAttributeMaxDynamicSharedMemorySize, FA_SMEM_BYTES);

    // 1) h = LN(x)
    ln_kernel<<<MR, 256>>>(x, g1, be1, h);

    // 2) Q projection
    gemm4<1, 0><<<dim3(Hc / 128, MR / 128), 256>>>(
        h, Hc, Wq, Hc, q, Hc, Hc, bq, nullptr, nullptr, nullptr, nullptr);

    // 3) K + V projections fused (grid.x = 8)
    gemm4<1, 1><<<dim3(2 * KVc / 128, MR / 128), 256>>>(
        h, Hc, Wk, KVc, kq, KVc, Hc, bk, nullptr, Wv, bv, vq);

    // 4) fused flash attention -> o
    flash_kernel<<<dim3(16, NHEADZ), 512, FA_SMEM_BYTES>>>(q, kq, vq, mask, o);

    // 5) x1 = x + o @ Wo + bo
    gemm4<2, 0><<<dim3(Hc / 128, MR / 128), 256>>>(
        o, Hc, Wo, Hc, x1, Hc, Hc, bo, x, nullptr, nullptr, nullptr);

    // 6) h2 = LN(x1)
    ln_kernel<<<MR, 256>>>(x1, g2, be2, h2);

    // 7) m1 = gelu(h2 @ W1 + b1)
    gemm4<3, 0><<<dim3(FFc / 128, MR / 128), 256>>>(
        h2, Hc, W1, FFc, m1, FFc, Hc, b1, nullptr, nullptr, nullptr, nullptr);

    // 8) out = x1 + m1 @ W2 + b2
    gemm4<2, 0><<<dim3(Hc / 128, MR / 128), 256>>>(
        m1, FFc, W2, Hc, out, Hc, FFc, b2, x1, nullptr, nullptr, nullptr);
}